// round 7
// baseline (speedup 1.0000x reference)
#include <cuda_runtime.h>
#include <math.h>

#define NROWS 6144
#define KDIM  128
#define NCLS  200
#define RPB   8
#define NBLK  (NROWS / RPB)      // 768
#define NTHR  1024
#define NWARP (NTHR / 32)        // 32
#define SIMCAP 128
#define QBLKS 192

// GEMM tiling
#define GTM 64
#define GTN 512
#define GTHR 512
#define GKC 16                          // k-chunk staged in smem
#define GB_APK 0                        // u64[128][64] = 64 KB
#define GB_B   65536                    // float[2][16][512] = 64 KB
#define GSMEM  131072

// ---- stats kernel shared memory layout (byte offsets) ----
#define SM_ROWS   0                                   // [8][6144] f32 = 196608
#define SM_SLAB   196608                              // 6144
#define SM_SIMM   202752                              // 6144
#define SM_HIST   208896                              // [8][256] int = 8192
#define SM_VHIST  217088                              // [8][256] f32 = 8192
#define SM_SIMV   225280                              // [8][128] f32 = 4096
#define SM_SCNT   229376                              // 32
#define SM_MISC   229408                              // 512
#define SM_WSCR   229920                              // 1024
#define SMEM_BYTES 230944

#define MISC_SUMS  (SM_MISC + 0)
#define MISC_SUMD  (SM_MISC + 32)
#define MISC_SGT   (SM_MISC + 64)
#define MISC_VSUF  (SM_MISC + 96)
#define MISC_SMIN  (SM_MISC + 128)
#define MISC_BP    (SM_MISC + 160)
#define MISC_BPD   (SM_MISC + 192)
#define MISC_LP    (SM_MISC + 224)
#define MISC_LN    (SM_MISC + 256)
#define MISC_NSIM  (SM_MISC + 288)
#define MISC_KSEL  (SM_MISC + 320)
#define MISC_KK    (SM_MISC + 352)
#define MISC_PFX   (SM_MISC + 384)
#define MISC_EP    (SM_MISC + 448)
#define MISC_EN    (SM_MISC + 480)

static __device__ float g_uhT[KDIM * NROWS];            // transposed tanh(u): [k][j]
static __device__ float g_inner[(size_t)NROWS * NROWS]; // full inner-product matrix
static __device__ int   g_label[NROWS];
static __device__ float g_rowpos[NROWS];
static __device__ float g_rowneg[NROWS];
static __device__ int   g_valid[NROWS];
static __device__ float g_qpart[QBLKS];

__device__ __forceinline__ unsigned f2key(float f) {
    unsigned u = __float_as_uint(f);
    return u ^ ((unsigned)(((int)u) >> 31) | 0x80000000u);
}
__device__ __forceinline__ float clip64(float x) { return fminf(fmaxf(x, 0.f), 64.f); }
__device__ __forceinline__ float softplus_f(float x) {
    return fmaxf(x, 0.f) + __logf(1.f + __expf(-fabsf(x)));
}
__device__ __forceinline__ unsigned long long packww(float w) {
    unsigned long long r;
    asm("mov.b64 %0, {%1, %1};" : "=l"(r) : "f"(w));
    return r;
}
__device__ __forceinline__ unsigned s2u(const void* p) {
    unsigned a;
    asm("{ .reg .u64 t; cvta.to.shared.u64 t, %1; cvt.u32.u64 %0, t; }"
        : "=r"(a) : "l"(p));
    return a;
}
__device__ __forceinline__ void cpasync16(unsigned saddr, const void* g) {
    asm volatile("cp.async.cg.shared.global [%0], [%1], 16;" :: "r"(saddr), "l"(g));
}
// warp-aggregated shared-memory histogram increment (bins cluster heavily)
__device__ __forceinline__ void aggHistAdd(int* hist, int idx) {
    unsigned active = __activemask();
    unsigned mask = __match_any_sync(active, idx);
    int leader = __ffs(mask) - 1;
    if ((int)(threadIdx.x & 31) == leader)
        atomicAdd(hist + idx, __popc(mask));
}

// deterministic 8-value block reductions (fixed order)
__device__ __forceinline__ void blockSum8F(float v[8], float* wscr, float* out8, int tid) {
    int lane = tid & 31, wid = tid >> 5;
    #pragma unroll
    for (int r = 0; r < 8; r++) {
        #pragma unroll
        for (int o = 16; o > 0; o >>= 1) v[r] += __shfl_xor_sync(0xFFFFFFFFu, v[r], o);
    }
    if (lane == 0) {
        #pragma unroll
        for (int r = 0; r < 8; r++) wscr[wid * 8 + r] = v[r];
    }
    __syncthreads();
    if (tid < 8) {
        float s = 0.f;
        #pragma unroll
        for (int w = 0; w < NWARP; w++) s += wscr[w * 8 + tid];
        out8[tid] = s;
    }
    __syncthreads();
}
__device__ __forceinline__ void blockSum8I(int v[8], int* wscr, int* out8, int tid) {
    int lane = tid & 31, wid = tid >> 5;
    #pragma unroll
    for (int r = 0; r < 8; r++) {
        #pragma unroll
        for (int o = 16; o > 0; o >>= 1) v[r] += __shfl_xor_sync(0xFFFFFFFFu, v[r], o);
    }
    if (lane == 0) {
        #pragma unroll
        for (int r = 0; r < 8; r++) wscr[wid * 8 + r] = v[r];
    }
    __syncthreads();
    if (tid < 8) {
        int s = 0;
        #pragma unroll
        for (int w = 0; w < NWARP; w++) s += wscr[w * 8 + tid];
        out8[tid] = s;
    }
    __syncthreads();
}

// warp-cooperative reverse scan over one 256-bin histogram row.
__device__ __forceinline__ int radixPick(const int* histrow, int kk, int lane,
                                         int* kknext_out) {
    int topbin = 255 - lane * 8;
    int csum = 0;
    #pragma unroll
    for (int b = 0; b < 8; b++) csum += histrow[topbin - b];
    int incl = csum;
    #pragma unroll
    for (int o = 1; o < 32; o <<= 1) {
        int t = __shfl_up_sync(0xFFFFFFFFu, incl, o);
        if (lane >= o) incl += t;
    }
    int excl = incl - csum;
    int hit = (excl < kk && kk <= incl) ? 1 : 0;
    unsigned who = __ballot_sync(0xFFFFFFFFu, hit);
    int src = __ffs(who) - 1;
    int bfound = 0, kknext = 0;
    if (hit) {
        int running = excl;
        #pragma unroll
        for (int b = 0; b < 8; b++) {
            int bin = topbin - b;
            int c = histrow[bin];
            running += c;
            if (running >= kk) { bfound = bin; kknext = kk - (running - c); break; }
        }
    }
    bfound = __shfl_sync(0xFFFFFFFFu, bfound, src);
    kknext = __shfl_sync(0xFFFFFFFFu, kknext, src);
    *kknext_out = kknext;
    return bfound;
}

// ---------------- kernel 0: tanh + quantization partials + transpose ----------
__global__ void __launch_bounds__(256) tanh_kernel(const float* __restrict__ u) {
    __shared__ float tile[32][129];
    __shared__ float scr[8];
    const int tid = threadIdx.x;
    const int i0 = blockIdx.x * 32;
    float q = 0.f;
    for (int idx = tid; idx < 32 * KDIM; idx += 256) {
        int r = idx >> 7, k = idx & 127;
        float x = tanhf(u[(i0 + r) * KDIM + k]);
        tile[r][k] = x;
        float s = (x > 0.f) ? 1.f : ((x < 0.f) ? -1.f : 0.f);
        float d = x - s;
        q += d * d;
    }
    __syncthreads();
    for (int idx = tid; idx < 32 * KDIM; idx += 256) {
        int k = idx >> 5, i = idx & 31;
        g_uhT[k * NROWS + i0 + i] = tile[i][k];
    }
    #pragma unroll
    for (int o = 16; o > 0; o >>= 1) q += __shfl_xor_sync(0xFFFFFFFFu, q, o);
    if ((tid & 31) == 0) scr[tid >> 5] = q;
    __syncthreads();
    if (tid == 0) {
        float s = 0.f;
        for (int w = 0; w < 8; w++) s += scr[w];
        g_qpart[blockIdx.x] = s;
    }
}

// ---------------- kernel 1: one-hot -> label ---------------------------------
__global__ void label_kernel(const int* __restrict__ y) {
    int i = blockIdx.x * blockDim.x + threadIdx.x;
    if (i < NROWS) {
        int lab = 0;
        const int* yr = y + (size_t)i * NCLS;
        for (int c = 0; c < NCLS; c++) {
            if (yr[c] != 0) { lab = c; break; }
        }
        g_label[i] = lab;
    }
}

// ---------------- kernel 2: GEMM inner = uh @ uh^T  --------------------------
// 64i x 512j tile, 512 threads, 8i x 8j per thread.
// B staged through smem in 16-k chunks (cp.async double-buffer) so each B
// element hits L2 exactly once per block; output stored evict-first (.cs).
__global__ void __launch_bounds__(GTHR, 1) gemm_kernel() {
    extern __shared__ unsigned char gsm[];
    unsigned long long* apk = (unsigned long long*)(gsm + GB_APK);
    float* bbuf = (float*)(gsm + GB_B);
    const unsigned bsm = s2u(bbuf);
    const int tid = threadIdx.x;
    const int i0 = blockIdx.x * GTM;
    const int j0 = blockIdx.y * GTN;

    // stage A packed (w,w)
    for (int t = tid; t < KDIM * GTM; t += GTHR) {
        int k = t >> 6, i = t & 63;
        apk[k * GTM + i] = packww(g_uhT[(size_t)k * NROWS + i0 + i]);
    }

    const float* Bsrc = g_uhT + j0;
    // stage chunk 0
    {
        const float* src = Bsrc;
        #pragma unroll
        for (int t = 0; t < 4; t++) {
            int u = tid + t * GTHR;           // 0..2047
            int k = u >> 7;
            int jj = (u & 127) * 4;
            cpasync16(bsm + (unsigned)(k * GTN + jj) * 4u,
                      src + (size_t)k * NROWS + jj);
        }
        asm volatile("cp.async.commit_group;" ::: "memory");
    }
    __syncthreads();   // apk ready

    const int tjj = (tid & 63) * 8;
    const int tii = (tid >> 6) * 8;

    unsigned long long acc[8][4];
    #pragma unroll
    for (int i = 0; i < 8; i++)
        #pragma unroll
        for (int c = 0; c < 4; c++) acc[i][c] = 0ull;

    for (int c = 0; c < KDIM / GKC; c++) {
        const int cur = c & 1;
        if (c + 1 < KDIM / GKC) {
            const float* src = Bsrc + (size_t)(c + 1) * GKC * NROWS;
            unsigned dstb = bsm + (unsigned)((cur ^ 1) * GKC * GTN) * 4u;
            #pragma unroll
            for (int t = 0; t < 4; t++) {
                int u = tid + t * GTHR;
                int k = u >> 7;
                int jj = (u & 127) * 4;
                cpasync16(dstb + (unsigned)(k * GTN + jj) * 4u,
                          src + (size_t)k * NROWS + jj);
            }
            asm volatile("cp.async.commit_group;" ::: "memory");
            asm volatile("cp.async.wait_group 1;" ::: "memory");
        } else {
            asm volatile("cp.async.wait_group 0;" ::: "memory");
        }
        __syncthreads();

        const float* bb = bbuf + cur * GKC * GTN + tjj;
        #pragma unroll
        for (int kk = 0; kk < GKC; kk++) {
            const ulonglong2* bp2 = (const ulonglong2*)(bb + kk * GTN);
            ulonglong2 b01 = bp2[0];
            ulonglong2 b23 = bp2[1];
            const int k = c * GKC + kk;
            #pragma unroll
            for (int i = 0; i < 8; i++) {
                unsigned long long a = apk[k * GTM + tii + i];
                asm("fma.rn.f32x2 %0, %1, %2, %0;" : "+l"(acc[i][0]) : "l"(b01.x), "l"(a));
                asm("fma.rn.f32x2 %0, %1, %2, %0;" : "+l"(acc[i][1]) : "l"(b01.y), "l"(a));
                asm("fma.rn.f32x2 %0, %1, %2, %0;" : "+l"(acc[i][2]) : "l"(b23.x), "l"(a));
                asm("fma.rn.f32x2 %0, %1, %2, %0;" : "+l"(acc[i][3]) : "l"(b23.y), "l"(a));
            }
        }
        __syncthreads();
    }

    #pragma unroll
    for (int i = 0; i < 8; i++) {
        size_t base = (size_t)(i0 + tii + i) * NROWS + j0 + tjj;
        float4 v1, v2;
        v1.x = __uint_as_float((unsigned)(acc[i][0] & 0xFFFFFFFFull));
        v1.y = __uint_as_float((unsigned)(acc[i][0] >> 32));
        v1.z = __uint_as_float((unsigned)(acc[i][1] & 0xFFFFFFFFull));
        v1.w = __uint_as_float((unsigned)(acc[i][1] >> 32));
        v2.x = __uint_as_float((unsigned)(acc[i][2] & 0xFFFFFFFFull));
        v2.y = __uint_as_float((unsigned)(acc[i][2] >> 32));
        v2.z = __uint_as_float((unsigned)(acc[i][3] & 0xFFFFFFFFull));
        v2.w = __uint_as_float((unsigned)(acc[i][3] >> 32));
        __stcs((float4*)(g_inner + base), v1);
        __stcs((float4*)(g_inner + base + 4), v2);
    }
}

// ---------------- kernel 3: stats + loss over 8-row slabs --------------------
__global__ void __launch_bounds__(NTHR, 1) stats_loss_kernel() {
    extern __shared__ unsigned char sm[];
    float* rows          = (float*)(sm + SM_ROWS);
    unsigned char* slab  = (unsigned char*)(sm + SM_SLAB);
    unsigned char* simm  = (unsigned char*)(sm + SM_SIMM);
    int*   hist          = (int*)(sm + SM_HIST);
    float* vhist         = (float*)(sm + SM_VHIST);
    float* simv          = (float*)(sm + SM_SIMV);
    int*   scnt          = (int*)(sm + SM_SCNT);
    float* sumS8         = (float*)(sm + MISC_SUMS);
    float* sumD8         = (float*)(sm + MISC_SUMD);
    float* sgt8          = (float*)(sm + MISC_SGT);
    float* vsuf8         = (float*)(sm + MISC_VSUF);
    float* sMin8         = (float*)(sm + MISC_SMIN);
    float* BP8           = (float*)(sm + MISC_BP);
    float* BPd8          = (float*)(sm + MISC_BPD);
    float* lp8           = (float*)(sm + MISC_LP);
    float* ln8           = (float*)(sm + MISC_LN);
    int*   nsim8         = (int*)(sm + MISC_NSIM);
    int*   ksel8         = (int*)(sm + MISC_KSEL);
    int*   kk8           = (int*)(sm + MISC_KK);
    unsigned* pfx8       = (unsigned*)(sm + MISC_PFX);
    int*   ep8           = (int*)(sm + MISC_EP);
    int*   en8           = (int*)(sm + MISC_EN);
    float* wscrF         = (float*)(sm + SM_WSCR);
    int*   wscrI         = (int*)(sm + SM_WSCR);

    const int tid = threadIdx.x;
    const int lane = tid & 31, wid = tid >> 5;
    const int i0  = blockIdx.x * RPB;

    // ---- setup: slab (streaming), labels, zero hists ----
    {
        const float4* src = (const float4*)(g_inner + (size_t)i0 * NROWS);
        float4* dst = (float4*)rows;
        #pragma unroll 4
        for (int t = tid; t < RPB * NROWS / 4; t += NTHR) dst[t] = __ldcs(src + t);
    }
    for (int t = tid; t < NROWS; t += NTHR) slab[t] = (unsigned char)g_label[t];
    for (int t = tid; t < RPB * 256; t += NTHR) hist[t] = 0;
    __syncthreads();

    unsigned labr[8];
    #pragma unroll
    for (int r = 0; r < RPB; r++) labr[r] = slab[i0 + r];

    // ---- build similarity bitmask ----
    for (int j = tid; j < NROWS; j += NTHR) {
        unsigned lab = slab[j];
        unsigned m = 0;
        #pragma unroll
        for (int r = 0; r < RPB; r++) m |= (lab == labr[r]) ? (1u << r) : 0u;
        simm[j] = (unsigned char)m;
    }
    __syncthreads();

    const unsigned* m4p = (const unsigned*)simm;

    // ---- Sweep A: sums (branchless, r-outer, float4) ----
    {
        float sS[8], sD[8];
        #pragma unroll
        for (int r = 0; r < 8; r++) {
            float aS = 0.f, aD = 0.f;
            const float4* row4 = (const float4*)(rows + r * NROWS);
            for (int t = tid; t < NROWS / 4; t += NTHR) {
                float4 v = row4[t];
                unsigned m4 = m4p[t];
                bool s0 = (m4 >> r) & 1u;
                bool s1 = (m4 >> (8 + r)) & 1u;
                bool s2 = (m4 >> (16 + r)) & 1u;
                bool s3 = (m4 >> (24 + r)) & 1u;
                aS += s0 ? v.x : 0.f;  aD += s0 ? 0.f : v.x;
                aS += s1 ? v.y : 0.f;  aD += s1 ? 0.f : v.y;
                aS += s2 ? v.z : 0.f;  aD += s2 ? 0.f : v.z;
                aS += s3 ? v.w : 0.f;  aD += s3 ? 0.f : v.w;
            }
            sS[r] = aS; sD[r] = aD;
        }
        blockSum8F(sS, wscrF, sumS8, tid);
        blockSum8F(sD, wscrF, sumD8, tid);
    }

    // ---- A2: warp-specialized — collection (w0-7) | pass-0 hist (w8-31) ----
    if (wid < RPB) {
        int r = wid;
        int off = 0;
        for (int it = 0; it < NROWS / 32; it++) {
            int j = it * 32 + lane;
            bool s = (simm[j] >> r) & 1u;
            unsigned bal = __ballot_sync(0xFFFFFFFFu, s);
            if (s) {
                int pos = off + __popc(bal & ((1u << lane) - 1u));
                if (pos < SIMCAP) simv[r * SIMCAP + pos] = rows[r * NROWS + j];
            }
            off += __popc(bal);
        }
        if (lane == 0) scnt[r] = off;
    } else {
        int w = wid - 8;
        int r = w / 3, seg = w % 3;
        int base = seg * 2048;
        for (int it = 0; it < 64; it++) {
            int j = base + it * 32 + lane;
            bool dis = !((simm[j] >> r) & 1u);
            float v = rows[r * NROWS + j];
            if (dis) aggHistAdd(hist, r * 256 + (int)(f2key(v) >> 24));
        }
    }
    __syncthreads();

    // ---- sMin + radix init (threads 0..7) ----
    if (tid < RPB) {
        int r = tid;
        int ns = scnt[r];
        nsim8[r] = ns;
        int nd = NROWS - ns;
        int ks = nd - (nd * 9) / 10;
        if (ks < 1) ks = 1;
        ksel8[r] = ks;
        kk8[r]   = ks;
        int cnt = ns < SIMCAP ? ns : SIMCAP;
        int m = ns - (ns * 9) / 10;
        if (m < 1) m = 1;
        float* sv = simv + r * SIMCAP;
        float ssum = 0.f;
        for (int it = 0; it < m && it < cnt; it++) {
            int bi = it; float bv = sv[it];
            for (int t2 = it + 1; t2 < cnt; t2++) {
                float x = sv[t2];
                if (x < bv) { bv = x; bi = t2; }
            }
            sv[bi] = sv[it]; sv[it] = bv;
            ssum += bv;
        }
        sMin8[r] = clip64(ssum / (float)(m > 1 ? m : 1));
    }
    __syncthreads();

    // ---- radix pass-0 pick (warps 0..7) ----
    if (wid < RPB) {
        int kknext;
        int b0 = radixPick(hist + wid * 256, kk8[wid], lane, &kknext);
        if (lane == 0) { pfx8[wid] = (unsigned)b0; kk8[wid] = kknext; }
    }
    __syncthreads();

    // ---- re-zero hists for refine ----
    for (int t = tid; t < RPB * 256; t += NTHR) { hist[t] = 0; vhist[t] = 0.f; }
    __syncthreads();

    // ---- Sweep B: refine (r-outer), sum above byte-0 bin ----
    {
        float sg[8];
        #pragma unroll
        for (int r = 0; r < 8; r++) {
            unsigned p0 = pfx8[r];
            float accG = 0.f;
            const float4* row4 = (const float4*)(rows + r * NROWS);
            for (int t = tid; t < NROWS / 4; t += NTHR) {
                float4 v = row4[t];
                unsigned m4 = m4p[t];
                float ve[4] = {v.x, v.y, v.z, v.w};
                #pragma unroll
                for (int e = 0; e < 4; e++) {
                    bool dis = !((m4 >> (8 * e + r)) & 1u);
                    if (dis) {
                        unsigned key = f2key(ve[e]);
                        unsigned hi = key >> 24;
                        accG += (hi > p0) ? ve[e] : 0.f;
                        if (hi == p0) {
                            int bin = (int)((key >> 16) & 255u);
                            atomicAdd(&hist[r * 256 + bin], 1);
                            atomicAdd(&vhist[r * 256 + bin], ve[e]);
                        }
                    }
                }
            }
            sg[r] = accG;
        }
        blockSum8F(sg, wscrF, sgt8, tid);
    }

    // ---- pick1 + suffix value sum (warps 0..7) ----
    if (wid < RPB) {
        int kknext;
        int b1 = radixPick(hist + wid * 256, kk8[wid], lane, &kknext);
        int topbin = 255 - lane * 8;
        float vp = 0.f;
        #pragma unroll
        for (int b = 0; b < 8; b++) {
            int bin = topbin - b;
            if (bin > b1) vp += vhist[wid * 256 + bin];
        }
        #pragma unroll
        for (int o = 16; o > 0; o >>= 1) vp += __shfl_xor_sync(0xFFFFFFFFu, vp, o);
        if (lane == 0) {
            float bm = vhist[wid * 256 + b1] / (float)hist[wid * 256 + b1];
            vsuf8[wid] = vp + (float)kknext * bm;
        }
    }
    __syncthreads();

    // ---- thresholds BP/BPd ----
    if (tid < RPB) {
        int r = tid;
        int ns = nsim8[r], nd = NROWS - ns;
        int ks = ksel8[r];
        float dsum = sgt8[r] + vsuf8[r];
        float dMax = clip64(dsum / (float)(ks > 1 ? ks : 1));
        float meanS  = clip64(sumS8[r] / fmaxf((float)ns, 1.f));
        float meanDS = clip64(sumD8[r] / fmaxf((float)nd, 1.f));
        float sMin = sMin8[r];
        BP8[r]  = meanS  - (64.f - meanS) / 64.f * fabsf(meanS - dMax);
        BPd8[r] = meanDS + meanDS / 64.f * fabsf(meanDS - sMin);
    }
    __syncthreads();

    // ---- Sweep C: loss (branchless, r-outer) ----
    {
        const float C1 = -0.2871949906334119f;  // C_COEF = -ln(99)/16
        const float C2 = 2.f * C1;              // A_COEF * C_COEF (a == 2 exactly)
        float lp[8], ln_[8]; int ep[8], en[8];
        #pragma unroll
        for (int r = 0; r < 8; r++) {
            float bp = BP8[r], bpd = BPd8[r];
            float accP = 0.f, accN = 0.f;
            int cP = 0, cN = 0;
            const float4* row4 = (const float4*)(rows + r * NROWS);
            for (int t = tid; t < NROWS / 4; t += NTHR) {
                float4 v = row4[t];
                unsigned m4 = m4p[t];
                float ve[4] = {v.x, v.y, v.z, v.w};
                #pragma unroll
                for (int e = 0; e < 4; e++) {
                    bool sim = (m4 >> (8 * e + r)) & 1u;
                    float th = sim ? bp : bpd;
                    float dc = ve[e] - th;
                    bool pos = dc > 0.f;
                    float cpos = sim ? C1 : -C2;
                    float cneg = sim ? C2 : -C1;
                    float coef = pos ? cpos : cneg;
                    float sp = softplus_f(coef * dc);
                    bool eq = (dc == 0.f);
                    accP += (sim && !eq) ? sp : 0.f;
                    accN += (!sim && !eq) ? sp : 0.f;
                    cP += (sim && eq) ? 1 : 0;
                    cN += (!sim && eq) ? 1 : 0;
                }
            }
            lp[r] = accP; ln_[r] = accN; ep[r] = cP; en[r] = cN;
        }
        blockSum8F(lp, wscrF, lp8, tid);
        blockSum8F(ln_, wscrF, ln8, tid);
        blockSum8I(ep, wscrI, ep8, tid);
        blockSum8I(en, wscrI, en8, tid);
    }

    if (tid < RPB) {
        int r = tid;
        int ns = nsim8[r], nd = NROWS - ns;
        int cp = ns - ep8[r];
        int cn = nd - en8[r];
        g_rowpos[i0 + r] = lp8[r] / fmaxf((float)cp, 1.f);
        g_rowneg[i0 + r] = ln8[r] / fmaxf((float)cn, 1.f);
        g_valid[i0 + r]  = (ns > 0 && nd > 0) ? 1 : 0;
    }
}

// ---------------- kernel 4: final scalar -------------------------------------
__global__ void __launch_bounds__(256) final_kernel(float* __restrict__ out) {
    __shared__ float scrF[8];
    __shared__ int scrI[8];
    int tid = threadIdx.x;
    float ps = 0.f, ns = 0.f; int cv = 0;
    for (int i = tid; i < NROWS; i += 256) {
        if (g_valid[i]) { ps += g_rowpos[i]; ns += g_rowneg[i]; cv++; }
    }
    float q = 0.f;
    for (int i = tid; i < QBLKS; i += 256) q += g_qpart[i];
    #pragma unroll
    for (int o = 16; o > 0; o >>= 1) {
        ps += __shfl_xor_sync(0xFFFFFFFFu, ps, o);
        ns += __shfl_xor_sync(0xFFFFFFFFu, ns, o);
        cv += __shfl_xor_sync(0xFFFFFFFFu, cv, o);
        q  += __shfl_xor_sync(0xFFFFFFFFu, q, o);
    }
    if ((tid & 31) == 0) { scrF[tid >> 5] = ps; scrI[tid >> 5] = cv; }
    __syncthreads();
    __shared__ float scrF2[8]; __shared__ float scrF3[8];
    if ((tid & 31) == 0) { scrF2[tid >> 5] = ns; scrF3[tid >> 5] = q; }
    __syncthreads();
    if (tid == 0) {
        float psum = 0.f, nsum = 0.f, qs = 0.f; int cnt = 0;
        for (int w = 0; w < 8; w++) {
            psum += scrF[w]; nsum += scrF2[w]; qs += scrF3[w]; cnt += scrI[w];
        }
        float posL = (cnt > 0) ? psum / fmaxf((float)cnt, 1.f) : 0.f;
        float navL = (cnt > 0) ? nsum / fmaxf((float)cnt, 1.f) : 0.f;
        float ql = 0.1f * qs / (float)(NROWS * KDIM);
        out[0] = posL + navL + ql;
    }
}

extern "C" void kernel_launch(void* const* d_in, const int* in_sizes, int n_in,
                              void* d_out, int out_size) {
    const float* u = (const float*)d_in[0];
    const int*   y = (const int*)d_in[1];
    (void)in_sizes; (void)n_in; (void)out_size;

    cudaFuncSetAttribute(gemm_kernel,
                         cudaFuncAttributeMaxDynamicSharedMemorySize, GSMEM);
    cudaFuncSetAttribute(stats_loss_kernel,
                         cudaFuncAttributeMaxDynamicSharedMemorySize, SMEM_BYTES);

    tanh_kernel<<<QBLKS, 256>>>(u);
    label_kernel<<<(NROWS + 255) / 256, 256>>>(y);
    dim3 ggrid(NROWS / GTM, NROWS / GTN);     // (96, 12)
    gemm_kernel<<<ggrid, GTHR, GSMEM>>>();
    stats_loss_kernel<<<NBLK, NTHR, SMEM_BYTES>>>();
    final_kernel<<<1, 256>>>((float*)d_out);
}

// round 8
// speedup vs baseline: 1.1666x; 1.1666x over previous
#include <cuda_runtime.h>
#include <math.h>

#define NROWS 6144
#define KDIM  128
#define NCLS  200
#define RPB   8
#define NBLK  (NROWS / RPB)      // 768
#define NTHR  1024
#define NWARP (NTHR / 32)        // 32
#define SIMCAP 128
#define QBLKS 192

// GEMM tiling
#define GTM 64
#define GTN 512
#define GTHR 512
#define GSMEM (KDIM * GTM * 8)   // 65536

// ---- stats kernel shared memory layout (byte offsets) ----
#define SM_ROWS   0                                   // [8][6144] f32 = 196608
#define SM_SLAB   196608                              // 6144
#define SM_SIMM   202752                              // 6144
#define SM_HIST   208896                              // [8][256] int = 8192
#define SM_VHIST  217088                              // [8][256] f32 = 8192
#define SM_SIMV   225280                              // [8][128] f32 = 4096
#define SM_SCNT   229376                              // 32
#define SM_MISC   229408                              // 512
#define SM_WSCR   229920                              // 1024
#define SMEM_BYTES 230944

#define MISC_ROWS8 (SM_MISC + 0)
#define MISC_SUMS  (SM_MISC + 32)
#define MISC_SGT   (SM_MISC + 64)
#define MISC_VSUF  (SM_MISC + 96)
#define MISC_SMIN  (SM_MISC + 128)
#define MISC_BP    (SM_MISC + 160)
#define MISC_BPD   (SM_MISC + 192)
#define MISC_LP    (SM_MISC + 224)
#define MISC_LN    (SM_MISC + 256)
#define MISC_NSIM  (SM_MISC + 288)
#define MISC_KSEL  (SM_MISC + 320)
#define MISC_KK    (SM_MISC + 352)
#define MISC_PFX   (SM_MISC + 384)
#define MISC_EP    (SM_MISC + 448)
#define MISC_EN    (SM_MISC + 480)

static __device__ float g_uhT[KDIM * NROWS];            // transposed tanh(u): [k][j]
static __device__ float g_inner[(size_t)NROWS * NROWS]; // full inner-product matrix
static __device__ int   g_label[NROWS];
static __device__ float g_rowpos[NROWS];
static __device__ float g_rowneg[NROWS];
static __device__ int   g_valid[NROWS];
static __device__ float g_qpart[QBLKS];

__device__ __forceinline__ unsigned f2key(float f) {
    unsigned u = __float_as_uint(f);
    return u ^ ((unsigned)(((int)u) >> 31) | 0x80000000u);
}
__device__ __forceinline__ float clip64(float x) { return fminf(fmaxf(x, 0.f), 64.f); }
__device__ __forceinline__ float softplus_f(float x) {
    return fmaxf(x, 0.f) + __logf(1.f + __expf(-fabsf(x)));
}
__device__ __forceinline__ unsigned long long packww(float w) {
    unsigned long long r;
    asm("mov.b64 %0, {%1, %1};" : "=l"(r) : "f"(w));
    return r;
}
__device__ __forceinline__ unsigned s2u(const void* p) {
    unsigned a;
    asm("{ .reg .u64 t; cvta.to.shared.u64 t, %1; cvt.u32.u64 %0, t; }"
        : "=r"(a) : "l"(p));
    return a;
}
__device__ __forceinline__ void cpasync16(unsigned saddr, const void* g) {
    asm volatile("cp.async.cg.shared.global [%0], [%1], 16;" :: "r"(saddr), "l"(g));
}
#define ADD2(a, b) asm("add.rn.f32x2 %0, %0, %1;" : "+l"(a) : "l"(b))
__device__ __forceinline__ float u64lo(unsigned long long a) {
    return __uint_as_float((unsigned)(a & 0xFFFFFFFFull));
}
__device__ __forceinline__ float u64hi(unsigned long long a) {
    return __uint_as_float((unsigned)(a >> 32));
}
// warp-aggregated shared-memory histogram increment (bins cluster heavily)
__device__ __forceinline__ void aggHistAdd(int* hist, int idx) {
    unsigned active = __activemask();
    unsigned mask = __match_any_sync(active, idx);
    int leader = __ffs(mask) - 1;
    if ((int)(threadIdx.x & 31) == leader)
        atomicAdd(hist + idx, __popc(mask));
}

// deterministic 8-value block reductions (fixed order)
__device__ __forceinline__ void blockSum8F(float v[8], float* wscr, float* out8, int tid) {
    int lane = tid & 31, wid = tid >> 5;
    #pragma unroll
    for (int r = 0; r < 8; r++) {
        #pragma unroll
        for (int o = 16; o > 0; o >>= 1) v[r] += __shfl_xor_sync(0xFFFFFFFFu, v[r], o);
    }
    if (lane == 0) {
        #pragma unroll
        for (int r = 0; r < 8; r++) wscr[wid * 8 + r] = v[r];
    }
    __syncthreads();
    if (tid < 8) {
        float s = 0.f;
        #pragma unroll
        for (int w = 0; w < NWARP; w++) s += wscr[w * 8 + tid];
        out8[tid] = s;
    }
    __syncthreads();
}
__device__ __forceinline__ void blockSum8I(int v[8], int* wscr, int* out8, int tid) {
    int lane = tid & 31, wid = tid >> 5;
    #pragma unroll
    for (int r = 0; r < 8; r++) {
        #pragma unroll
        for (int o = 16; o > 0; o >>= 1) v[r] += __shfl_xor_sync(0xFFFFFFFFu, v[r], o);
    }
    if (lane == 0) {
        #pragma unroll
        for (int r = 0; r < 8; r++) wscr[wid * 8 + r] = v[r];
    }
    __syncthreads();
    if (tid < 8) {
        int s = 0;
        #pragma unroll
        for (int w = 0; w < NWARP; w++) s += wscr[w * 8 + tid];
        out8[tid] = s;
    }
    __syncthreads();
}

// warp-cooperative reverse scan over one 256-bin histogram row.
__device__ __forceinline__ int radixPick(const int* histrow, int kk, int lane,
                                         int* kknext_out) {
    int topbin = 255 - lane * 8;
    int csum = 0;
    #pragma unroll
    for (int b = 0; b < 8; b++) csum += histrow[topbin - b];
    int incl = csum;
    #pragma unroll
    for (int o = 1; o < 32; o <<= 1) {
        int t = __shfl_up_sync(0xFFFFFFFFu, incl, o);
        if (lane >= o) incl += t;
    }
    int excl = incl - csum;
    int hit = (excl < kk && kk <= incl) ? 1 : 0;
    unsigned who = __ballot_sync(0xFFFFFFFFu, hit);
    int src = __ffs(who) - 1;
    int bfound = 0, kknext = 0;
    if (hit) {
        int running = excl;
        #pragma unroll
        for (int b = 0; b < 8; b++) {
            int bin = topbin - b;
            int c = histrow[bin];
            running += c;
            if (running >= kk) { bfound = bin; kknext = kk - (running - c); break; }
        }
    }
    bfound = __shfl_sync(0xFFFFFFFFu, bfound, src);
    kknext = __shfl_sync(0xFFFFFFFFu, kknext, src);
    *kknext_out = kknext;
    return bfound;
}

// ---------------- kernel 0: tanh + quantization partials + transpose ----------
__global__ void __launch_bounds__(256) tanh_kernel(const float* __restrict__ u) {
    __shared__ float tile[32][129];
    __shared__ float scr[8];
    const int tid = threadIdx.x;
    const int i0 = blockIdx.x * 32;
    float q = 0.f;
    for (int idx = tid; idx < 32 * KDIM; idx += 256) {
        int r = idx >> 7, k = idx & 127;
        float x = tanhf(u[(i0 + r) * KDIM + k]);
        tile[r][k] = x;
        float s = (x > 0.f) ? 1.f : ((x < 0.f) ? -1.f : 0.f);
        float d = x - s;
        q += d * d;
    }
    __syncthreads();
    for (int idx = tid; idx < 32 * KDIM; idx += 256) {
        int k = idx >> 5, i = idx & 31;
        g_uhT[k * NROWS + i0 + i] = tile[i][k];
    }
    #pragma unroll
    for (int o = 16; o > 0; o >>= 1) q += __shfl_xor_sync(0xFFFFFFFFu, q, o);
    if ((tid & 31) == 0) scr[tid >> 5] = q;
    __syncthreads();
    if (tid == 0) {
        float s = 0.f;
        for (int w = 0; w < 8; w++) s += scr[w];
        g_qpart[blockIdx.x] = s;
    }
}

// ---------------- kernel 1: one-hot -> label (warp per row) ------------------
__global__ void __launch_bounds__(256) label_kernel(const int* __restrict__ y) {
    int w = (blockIdx.x * blockDim.x + threadIdx.x) >> 5;
    int lane = threadIdx.x & 31;
    if (w < NROWS) {
        const int* yr = y + (size_t)w * NCLS;
        int lab = 0;
        for (int c = lane; c < NCLS; c += 32)
            if (yr[c] != 0) lab = c;
        #pragma unroll
        for (int o = 16; o > 0; o >>= 1)
            lab = max(lab, __shfl_xor_sync(0xFFFFFFFFu, lab, o));
        if (lane == 0) g_label[w] = lab;
    }
}

// ---------------- kernel 2: GEMM inner = uh @ uh^T  --------------------------
// 64i x 512j tile, 512 threads, 8i x 8j per thread. B register-prefetched at
// distance 2; output stored evict-first (.cs) so the 151 MB stream does not
// evict g_uhT from L2.
__global__ void __launch_bounds__(GTHR, 1) gemm_kernel() {
    extern __shared__ unsigned long long apk[];   // [KDIM][GTM] (a,a)-packed
    const int tid = threadIdx.x;
    const int i0 = blockIdx.x * GTM;
    const int j0 = blockIdx.y * GTN;

    for (int t = tid; t < KDIM * GTM; t += GTHR) {
        int k = t >> 6, i = t & 63;
        apk[k * GTM + i] = packww(g_uhT[(size_t)k * NROWS + i0 + i]);
    }
    __syncthreads();

    const int tjj = (tid & 63) * 8;
    const int tii = (tid >> 6) * 8;
    const float* Bp = g_uhT + (size_t)j0 + tjj;

    unsigned long long acc[8][4];
    #pragma unroll
    for (int i = 0; i < 8; i++)
        #pragma unroll
        for (int c = 0; c < 4; c++) acc[i][c] = 0ull;

    ulonglong2 b01[2], b23[2];
    b01[0] = *(const ulonglong2*)(Bp);
    b23[0] = *(const ulonglong2*)(Bp + 4);
    b01[1] = *(const ulonglong2*)(Bp + (size_t)NROWS);
    b23[1] = *(const ulonglong2*)(Bp + (size_t)NROWS + 4);

    #pragma unroll 2
    for (int k = 0; k < KDIM; k++) {
        const int p = k & 1;
        ulonglong2 cb01 = b01[p], cb23 = b23[p];
        if (k + 2 < KDIM) {
            b01[p] = *(const ulonglong2*)(Bp + (size_t)(k + 2) * NROWS);
            b23[p] = *(const ulonglong2*)(Bp + (size_t)(k + 2) * NROWS + 4);
        }
        #pragma unroll
        for (int i = 0; i < 8; i++) {
            unsigned long long a = apk[k * GTM + tii + i];
            asm("fma.rn.f32x2 %0, %1, %2, %0;" : "+l"(acc[i][0]) : "l"(cb01.x), "l"(a));
            asm("fma.rn.f32x2 %0, %1, %2, %0;" : "+l"(acc[i][1]) : "l"(cb01.y), "l"(a));
            asm("fma.rn.f32x2 %0, %1, %2, %0;" : "+l"(acc[i][2]) : "l"(cb23.x), "l"(a));
            asm("fma.rn.f32x2 %0, %1, %2, %0;" : "+l"(acc[i][3]) : "l"(cb23.y), "l"(a));
        }
    }

    #pragma unroll
    for (int i = 0; i < 8; i++) {
        size_t base = (size_t)(i0 + tii + i) * NROWS + j0 + tjj;
        float4 v1, v2;
        v1.x = u64lo(acc[i][0]); v1.y = u64hi(acc[i][0]);
        v1.z = u64lo(acc[i][1]); v1.w = u64hi(acc[i][1]);
        v2.x = u64lo(acc[i][2]); v2.y = u64hi(acc[i][2]);
        v2.z = u64lo(acc[i][3]); v2.w = u64hi(acc[i][3]);
        __stcs((float4*)(g_inner + base), v1);
        __stcs((float4*)(g_inner + base + 4), v2);
    }
}

// ---------------- kernel 3: stats + loss over 8-row slabs --------------------
__global__ void __launch_bounds__(NTHR, 1) stats_loss_kernel() {
    extern __shared__ unsigned char sm[];
    float* rows          = (float*)(sm + SM_ROWS);
    unsigned char* slab  = (unsigned char*)(sm + SM_SLAB);
    unsigned char* simm  = (unsigned char*)(sm + SM_SIMM);
    int*   hist          = (int*)(sm + SM_HIST);
    float* vhist         = (float*)(sm + SM_VHIST);
    float* simv          = (float*)(sm + SM_SIMV);
    int*   scnt          = (int*)(sm + SM_SCNT);
    float* rows8         = (float*)(sm + MISC_ROWS8);
    float* sumS8         = (float*)(sm + MISC_SUMS);
    float* sgt8          = (float*)(sm + MISC_SGT);
    float* vsuf8         = (float*)(sm + MISC_VSUF);
    float* sMin8         = (float*)(sm + MISC_SMIN);
    float* BP8           = (float*)(sm + MISC_BP);
    float* BPd8          = (float*)(sm + MISC_BPD);
    float* lp8           = (float*)(sm + MISC_LP);
    float* ln8           = (float*)(sm + MISC_LN);
    int*   nsim8         = (int*)(sm + MISC_NSIM);
    int*   ksel8         = (int*)(sm + MISC_KSEL);
    int*   kk8           = (int*)(sm + MISC_KK);
    unsigned* pfx8       = (unsigned*)(sm + MISC_PFX);
    int*   ep8           = (int*)(sm + MISC_EP);
    int*   en8           = (int*)(sm + MISC_EN);
    float* wscrF         = (float*)(sm + SM_WSCR);
    int*   wscrI         = (int*)(sm + SM_WSCR);

    const int tid = threadIdx.x;
    const int lane = tid & 31, wid = tid >> 5;
    const int i0  = blockIdx.x * RPB;

    // ---- async slab load, overlapped with labels/mask/hist setup ----
    {
        const unsigned rbase = s2u(rows);
        const float* src = g_inner + (size_t)i0 * NROWS;
        #pragma unroll
        for (int i = 0; i < 12; i++) {
            int idx = tid + i * NTHR;   // float4 index
            cpasync16(rbase + (unsigned)idx * 16u, src + (size_t)idx * 4);
        }
        asm volatile("cp.async.commit_group;" ::: "memory");
    }
    for (int t = tid; t < NROWS; t += NTHR) slab[t] = (unsigned char)g_label[t];
    for (int t = tid; t < RPB * 256; t += NTHR) hist[t] = 0;
    if (tid < RPB) scnt[tid] = 0;
    __syncthreads();   // slab (labels) visible

    unsigned labr[8];
    #pragma unroll
    for (int r = 0; r < RPB; r++) labr[r] = slab[i0 + r];

    for (int j = tid; j < NROWS; j += NTHR) {
        unsigned lab = slab[j];
        unsigned m = 0;
        #pragma unroll
        for (int r = 0; r < RPB; r++) m |= (lab == labr[r]) ? (1u << r) : 0u;
        simm[j] = (unsigned char)m;
    }
    asm volatile("cp.async.wait_group 0;" ::: "memory");
    __syncthreads();   // rows + simm ready

    // ---- rowsum sweep (mask-free, packed f32x2) ----
    {
        float rs[8];
        #pragma unroll
        for (int r = 0; r < 8; r++) {
            unsigned long long a = 0ull;
            const ulonglong2* p = (const ulonglong2*)(rows + r * NROWS);
            for (int t = tid; t < NROWS / 4; t += NTHR) {
                ulonglong2 v = p[t];
                ADD2(a, v.x);
                ADD2(a, v.y);
            }
            rs[r] = u64lo(a) + u64hi(a);
        }
        blockSum8F(rs, wscrF, rows8, tid);
    }

    // ---- pass-0: warp-specialized — collection (w0-7) | count hist (w8-31) ----
    if (wid < RPB) {
        int r = wid;
        int off = 0;
        for (int it = 0; it < NROWS / 32; it++) {
            int j = it * 32 + lane;
            bool s = (simm[j] >> r) & 1u;
            unsigned bal = __ballot_sync(0xFFFFFFFFu, s);
            if (s) {
                int pos = off + __popc(bal & ((1u << lane) - 1u));
                if (pos < SIMCAP) simv[r * SIMCAP + pos] = rows[r * NROWS + j];
            }
            off += __popc(bal);
        }
        if (lane == 0) scnt[r] = off;
    } else {
        int w = wid - 8;
        int r = w / 3, seg = w % 3;
        int base = seg * 2048;
        for (int it = 0; it < 64; it++) {
            int j = base + it * 32 + lane;
            bool dis = !((simm[j] >> r) & 1u);
            float v = rows[r * NROWS + j];
            if (dis) aggHistAdd(hist, r * 256 + (int)(f2key(v) >> 24));
        }
    }
    __syncthreads();

    // ---- sumS + sMin + radix init (threads 0..7) ----
    if (tid < RPB) {
        int r = tid;
        int ns = scnt[r];
        nsim8[r] = ns;
        int nd = NROWS - ns;
        int ks = nd - (nd * 9) / 10;
        if (ks < 1) ks = 1;
        ksel8[r] = ks;
        kk8[r]   = ks;
        int cnt = ns < SIMCAP ? ns : SIMCAP;
        float* sv = simv + r * SIMCAP;
        float sS = 0.f;
        for (int i = 0; i < cnt; i++) sS += sv[i];
        sumS8[r] = sS;
        int m = ns - (ns * 9) / 10;
        if (m < 1) m = 1;
        float ssum = 0.f;
        for (int it = 0; it < m && it < cnt; it++) {
            int bi = it; float bv = sv[it];
            for (int t2 = it + 1; t2 < cnt; t2++) {
                float x = sv[t2];
                if (x < bv) { bv = x; bi = t2; }
            }
            sv[bi] = sv[it]; sv[it] = bv;
            ssum += bv;
        }
        sMin8[r] = clip64(ssum / (float)(m > 1 ? m : 1));
    }
    __syncthreads();

    // ---- radix pass-0 pick (warps 0..7) ----
    if (wid < RPB) {
        int kknext;
        int b0 = radixPick(hist + wid * 256, kk8[wid], lane, &kknext);
        if (lane == 0) { pfx8[wid] = (unsigned)b0; kk8[wid] = kknext; }
    }
    __syncthreads();

    for (int t = tid; t < RPB * 256; t += NTHR) { hist[t] = 0; vhist[t] = 0.f; }
    __syncthreads();

    // ---- refine sweep (j-outer): sum above byte-0 bin, hist inside bin ----
    {
        unsigned p0[8];
        #pragma unroll
        for (int r = 0; r < 8; r++) p0[r] = pfx8[r];
        float sg[8];
        #pragma unroll
        for (int r = 0; r < 8; r++) sg[r] = 0.f;
        for (int j = tid; j < NROWS; j += NTHR) {
            unsigned m = simm[j];
            const float* rj = rows + j;
            #pragma unroll
            for (int r = 0; r < RPB; r++) {
                if (!((m >> r) & 1u)) {
                    float v = rj[r * NROWS];
                    unsigned key = f2key(v);
                    unsigned hi = key >> 24;
                    sg[r] += (hi > p0[r]) ? v : 0.f;
                    if (hi == p0[r]) {
                        int bin = (int)((key >> 16) & 255u);
                        atomicAdd(&hist[r * 256 + bin], 1);
                        atomicAdd(&vhist[r * 256 + bin], v);
                    }
                }
            }
        }
        blockSum8F(sg, wscrF, sgt8, tid);
    }

    // ---- pick1 + suffix value sum (warps 0..7) ----
    if (wid < RPB) {
        int kknext;
        int b1 = radixPick(hist + wid * 256, kk8[wid], lane, &kknext);
        int topbin = 255 - lane * 8;
        float vp = 0.f;
        #pragma unroll
        for (int b = 0; b < 8; b++) {
            int bin = topbin - b;
            if (bin > b1) vp += vhist[wid * 256 + bin];
        }
        #pragma unroll
        for (int o = 16; o > 0; o >>= 1) vp += __shfl_xor_sync(0xFFFFFFFFu, vp, o);
        if (lane == 0) {
            float bm = vhist[wid * 256 + b1] / (float)hist[wid * 256 + b1];
            vsuf8[wid] = vp + (float)kknext * bm;
        }
    }
    __syncthreads();

    // ---- thresholds BP/BPd ----
    if (tid < RPB) {
        int r = tid;
        int ns = nsim8[r], nd = NROWS - ns;
        int ks = ksel8[r];
        float sumD = rows8[r] - sumS8[r];
        float dsum = sgt8[r] + vsuf8[r];
        float dMax = clip64(dsum / (float)(ks > 1 ? ks : 1));
        float meanS  = clip64(sumS8[r] / fmaxf((float)ns, 1.f));
        float meanDS = clip64(sumD / fmaxf((float)nd, 1.f));
        float sMin = sMin8[r];
        BP8[r]  = meanS  - (64.f - meanS) / 64.f * fabsf(meanS - dMax);
        BPd8[r] = meanDS + meanDS / 64.f * fabsf(meanDS - sMin);
    }
    __syncthreads();

    // ---- loss sweep (j-outer, branchless body, predicated accumulate) ----
    {
        const float C1 = -0.2871949906334119f;  // C_COEF = -ln(99)/16
        const float C2 = 2.f * C1;              // A_COEF * C_COEF (a == 2 exactly)
        float bp[8], bpd[8];
        #pragma unroll
        for (int r = 0; r < 8; r++) { bp[r] = BP8[r]; bpd[r] = BPd8[r]; }
        float lp[8], ln_[8]; int ep[8], en[8];
        #pragma unroll
        for (int r = 0; r < 8; r++) { lp[r] = 0.f; ln_[r] = 0.f; ep[r] = 0; en[r] = 0; }
        for (int j = tid; j < NROWS; j += NTHR) {
            unsigned m = simm[j];
            const float* rj = rows + j;
            #pragma unroll
            for (int r = 0; r < RPB; r++) {
                float v = rj[r * NROWS];
                bool sim = (m >> r) & 1u;
                float th  = sim ? bp[r] : bpd[r];
                float dc  = v - th;
                float cpos = sim ? C1 : -C2;
                float cneg = sim ? C2 : -C1;
                float f = ((dc > 0.f) ? cpos : cneg) * dc;
                float sp = softplus_f(f);
                bool eq = (dc == 0.f);
                if (sim) { if (eq) ep[r]++; else lp[r] += sp; }
                else     { if (eq) en[r]++; else ln_[r] += sp; }
            }
        }
        blockSum8F(lp, wscrF, lp8, tid);
        blockSum8F(ln_, wscrF, ln8, tid);
        blockSum8I(ep, wscrI, ep8, tid);
        blockSum8I(en, wscrI, en8, tid);
    }

    if (tid < RPB) {
        int r = tid;
        int ns = nsim8[r], nd = NROWS - ns;
        int cp = ns - ep8[r];
        int cn = nd - en8[r];
        g_rowpos[i0 + r] = lp8[r] / fmaxf((float)cp, 1.f);
        g_rowneg[i0 + r] = ln8[r] / fmaxf((float)cn, 1.f);
        g_valid[i0 + r]  = (ns > 0 && nd > 0) ? 1 : 0;
    }
}

// ---------------- kernel 4: final scalar -------------------------------------
__global__ void __launch_bounds__(256) final_kernel(float* __restrict__ out) {
    __shared__ float scrF[8];
    __shared__ int scrI[8];
    int tid = threadIdx.x;
    float ps = 0.f, ns = 0.f; int cv = 0;
    for (int i = tid; i < NROWS; i += 256) {
        if (g_valid[i]) { ps += g_rowpos[i]; ns += g_rowneg[i]; cv++; }
    }
    float q = 0.f;
    for (int i = tid; i < QBLKS; i += 256) q += g_qpart[i];
    #pragma unroll
    for (int o = 16; o > 0; o >>= 1) {
        ps += __shfl_xor_sync(0xFFFFFFFFu, ps, o);
        ns += __shfl_xor_sync(0xFFFFFFFFu, ns, o);
        cv += __shfl_xor_sync(0xFFFFFFFFu, cv, o);
        q  += __shfl_xor_sync(0xFFFFFFFFu, q, o);
    }
    if ((tid & 31) == 0) { scrF[tid >> 5] = ps; scrI[tid >> 5] = cv; }
    __syncthreads();
    __shared__ float scrF2[8]; __shared__ float scrF3[8];
    if ((tid & 31) == 0) { scrF2[tid >> 5] = ns; scrF3[tid >> 5] = q; }
    __syncthreads();
    if (tid == 0) {
        float psum = 0.f, nsum = 0.f, qs = 0.f; int cnt = 0;
        for (int w = 0; w < 8; w++) {
            psum += scrF[w]; nsum += scrF2[w]; qs += scrF3[w]; cnt += scrI[w];
        }
        float posL = (cnt > 0) ? psum / fmaxf((float)cnt, 1.f) : 0.f;
        float navL = (cnt > 0) ? nsum / fmaxf((float)cnt, 1.f) : 0.f;
        float ql = 0.1f * qs / (float)(NROWS * KDIM);
        out[0] = posL + navL + ql;
    }
}

extern "C" void kernel_launch(void* const* d_in, const int* in_sizes, int n_in,
                              void* d_out, int out_size) {
    const float* u = (const float*)d_in[0];
    const int*   y = (const int*)d_in[1];
    (void)in_sizes; (void)n_in; (void)out_size;

    cudaFuncSetAttribute(gemm_kernel,
                         cudaFuncAttributeMaxDynamicSharedMemorySize, GSMEM);
    cudaFuncSetAttribute(stats_loss_kernel,
                         cudaFuncAttributeMaxDynamicSharedMemorySize, SMEM_BYTES);

    tanh_kernel<<<QBLKS, 256>>>(u);
    label_kernel<<<NROWS * 32 / 256, 256>>>(y);
    dim3 ggrid(NROWS / GTM, NROWS / GTN);     // (96, 12)
    gemm_kernel<<<ggrid, GTHR, GSMEM>>>();
    stats_loss_kernel<<<NBLK, NTHR, SMEM_BYTES>>>();
    final_kernel<<<1, 256>>>((float*)d_out);
}

// round 10
// speedup vs baseline: 1.3563x; 1.1626x over previous
#include <cuda_runtime.h>
#include <math.h>

#define NROWS 6144
#define KDIM  128
#define NCLS  200
#define RPB   8
#define NBLK  (NROWS / RPB)      // 768
#define NTHR  1024
#define NWARP (NTHR / 32)        // 32
#define SIMCAP 128
#define QBLKS 192

// symmetric GEMM tiling
#define GTT 128                  // square tile edge
#define GTHR2 256
#define GSMEM2 (KDIM * GTT * 8)  // 131072

// ---- stats kernel shared memory layout (byte offsets) ----
#define SM_ROWS   0                                   // [8][6144] f32 = 196608
#define SM_SLAB   196608                              // 6144
#define SM_SIMM   202752                              // 6144
#define SM_HIST   208896                              // [8][256] int = 8192
#define SM_VHIST  217088                              // [8][256] f32 = 8192
#define SM_SIMV   225280                              // [8][128] f32 = 4096
#define SM_SCNT   229376                              // 32
#define SM_MISC   229408                              // 512
#define SM_WSCR   229920                              // 1024
#define SMEM_BYTES 230944

#define MISC_ROWS8 (SM_MISC + 0)
#define MISC_SUMS  (SM_MISC + 32)
#define MISC_SGT   (SM_MISC + 64)
#define MISC_VSUF  (SM_MISC + 96)
#define MISC_SMIN  (SM_MISC + 128)
#define MISC_BP    (SM_MISC + 160)
#define MISC_BPD   (SM_MISC + 192)
#define MISC_LP    (SM_MISC + 224)
#define MISC_LN    (SM_MISC + 256)
#define MISC_NSIM  (SM_MISC + 288)
#define MISC_KSEL  (SM_MISC + 320)
#define MISC_KK    (SM_MISC + 352)
#define MISC_PFX   (SM_MISC + 384)
#define MISC_EP    (SM_MISC + 448)
#define MISC_EN    (SM_MISC + 480)

static __device__ float g_uhT[KDIM * NROWS];            // transposed tanh(u): [k][j]
static __device__ float g_inner[(size_t)NROWS * NROWS]; // full inner-product matrix
static __device__ int   g_label[NROWS];
static __device__ float g_rowpos[NROWS];
static __device__ float g_rowneg[NROWS];
static __device__ int   g_valid[NROWS];
static __device__ float g_qpart[QBLKS];

__device__ __forceinline__ unsigned f2key(float f) {
    unsigned u = __float_as_uint(f);
    return u ^ ((unsigned)(((int)u) >> 31) | 0x80000000u);
}
__device__ __forceinline__ float clip64(float x) { return fminf(fmaxf(x, 0.f), 64.f); }
__device__ __forceinline__ float softplus_f(float x) {
    return fmaxf(x, 0.f) + __logf(1.f + __expf(-fabsf(x)));
}
__device__ __forceinline__ unsigned long long packww(float w) {
    unsigned long long r;
    asm("mov.b64 %0, {%1, %1};" : "=l"(r) : "f"(w));
    return r;
}
__device__ __forceinline__ unsigned s2u(const void* p) {
    unsigned a;
    asm("{ .reg .u64 t; cvta.to.shared.u64 t, %1; cvt.u32.u64 %0, t; }"
        : "=r"(a) : "l"(p));
    return a;
}
__device__ __forceinline__ void cpasync16(unsigned saddr, const void* g) {
    asm volatile("cp.async.cg.shared.global [%0], [%1], 16;" :: "r"(saddr), "l"(g));
}
#define ADD2(a, b) asm("add.rn.f32x2 %0, %0, %1;" : "+l"(a) : "l"(b))
__device__ __forceinline__ float u64lo(unsigned long long a) {
    return __uint_as_float((unsigned)(a & 0xFFFFFFFFull));
}
__device__ __forceinline__ float u64hi(unsigned long long a) {
    return __uint_as_float((unsigned)(a >> 32));
}
__device__ __forceinline__ void aggHistAdd(int* hist, int idx) {
    unsigned active = __activemask();
    unsigned mask = __match_any_sync(active, idx);
    int leader = __ffs(mask) - 1;
    if ((int)(threadIdx.x & 31) == leader)
        atomicAdd(hist + idx, __popc(mask));
}

// deterministic 8-value block reductions (fixed order)
__device__ __forceinline__ void blockSum8F(float v[8], float* wscr, float* out8, int tid) {
    int lane = tid & 31, wid = tid >> 5;
    #pragma unroll
    for (int r = 0; r < 8; r++) {
        #pragma unroll
        for (int o = 16; o > 0; o >>= 1) v[r] += __shfl_xor_sync(0xFFFFFFFFu, v[r], o);
    }
    if (lane == 0) {
        #pragma unroll
        for (int r = 0; r < 8; r++) wscr[wid * 8 + r] = v[r];
    }
    __syncthreads();
    if (tid < 8) {
        float s = 0.f;
        #pragma unroll
        for (int w = 0; w < NWARP; w++) s += wscr[w * 8 + tid];
        out8[tid] = s;
    }
    __syncthreads();
}
__device__ __forceinline__ void blockSum8I(int v[8], int* wscr, int* out8, int tid) {
    int lane = tid & 31, wid = tid >> 5;
    #pragma unroll
    for (int r = 0; r < 8; r++) {
        #pragma unroll
        for (int o = 16; o > 0; o >>= 1) v[r] += __shfl_xor_sync(0xFFFFFFFFu, v[r], o);
    }
    if (lane == 0) {
        #pragma unroll
        for (int r = 0; r < 8; r++) wscr[wid * 8 + r] = v[r];
    }
    __syncthreads();
    if (tid < 8) {
        int s = 0;
        #pragma unroll
        for (int w = 0; w < NWARP; w++) s += wscr[w * 8 + tid];
        out8[tid] = s;
    }
    __syncthreads();
}

__device__ __forceinline__ int radixPick(const int* histrow, int kk, int lane,
                                         int* kknext_out) {
    int topbin = 255 - lane * 8;
    int csum = 0;
    #pragma unroll
    for (int b = 0; b < 8; b++) csum += histrow[topbin - b];
    int incl = csum;
    #pragma unroll
    for (int o = 1; o < 32; o <<= 1) {
        int t = __shfl_up_sync(0xFFFFFFFFu, incl, o);
        if (lane >= o) incl += t;
    }
    int excl = incl - csum;
    int hit = (excl < kk && kk <= incl) ? 1 : 0;
    unsigned who = __ballot_sync(0xFFFFFFFFu, hit);
    int src = __ffs(who) - 1;
    int bfound = 0, kknext = 0;
    if (hit) {
        int running = excl;
        #pragma unroll
        for (int b = 0; b < 8; b++) {
            int bin = topbin - b;
            int c = histrow[bin];
            running += c;
            if (running >= kk) { bfound = bin; kknext = kk - (running - c); break; }
        }
    }
    bfound = __shfl_sync(0xFFFFFFFFu, bfound, src);
    kknext = __shfl_sync(0xFFFFFFFFu, kknext, src);
    *kknext_out = kknext;
    return bfound;
}

// ---------------- kernel 0: tanh + quantization partials + transpose ----------
__global__ void __launch_bounds__(256) tanh_kernel(const float* __restrict__ u) {
    __shared__ float tile[32][129];
    __shared__ float scr[8];
    const int tid = threadIdx.x;
    const int i0 = blockIdx.x * 32;
    float q = 0.f;
    for (int idx = tid; idx < 32 * KDIM; idx += 256) {
        int r = idx >> 7, k = idx & 127;
        float x = tanhf(u[(i0 + r) * KDIM + k]);
        tile[r][k] = x;
        float s = (x > 0.f) ? 1.f : ((x < 0.f) ? -1.f : 0.f);
        float d = x - s;
        q += d * d;
    }
    __syncthreads();
    for (int idx = tid; idx < 32 * KDIM; idx += 256) {
        int k = idx >> 5, i = idx & 31;
        g_uhT[k * NROWS + i0 + i] = tile[i][k];
    }
    #pragma unroll
    for (int o = 16; o > 0; o >>= 1) q += __shfl_xor_sync(0xFFFFFFFFu, q, o);
    if ((tid & 31) == 0) scr[tid >> 5] = q;
    __syncthreads();
    if (tid == 0) {
        float s = 0.f;
        for (int w = 0; w < 8; w++) s += scr[w];
        g_qpart[blockIdx.x] = s;
    }
}

// ---------------- kernel 1: one-hot -> label (warp per row) ------------------
__global__ void __launch_bounds__(256) label_kernel(const int* __restrict__ y) {
    int w = (blockIdx.x * blockDim.x + threadIdx.x) >> 5;
    int lane = threadIdx.x & 31;
    if (w < NROWS) {
        const int* yr = y + (size_t)w * NCLS;
        int lab = 0;
        for (int c = lane; c < NCLS; c += 32)
            if (yr[c] != 0) lab = c;
        #pragma unroll
        for (int o = 16; o > 0; o >>= 1)
            lab = max(lab, __shfl_xor_sync(0xFFFFFFFFu, lab, o));
        if (lane == 0) g_label[w] = lab;
    }
}

// ---------------- kernel 2: SYMMETRIC GEMM inner = uh @ uh^T -----------------
// 128x128 tiles over the upper triangle only (it <= jt); off-diagonal tiles
// are stored twice (direct + transposed) -> half the FLOPs, same store bytes.
__global__ void __launch_bounds__(GTHR2, 1) gemm_sym_kernel() {
    extern __shared__ unsigned long long apk[];   // [KDIM][GTT] (a,a)-packed
    const int it = blockIdx.x, jt = blockIdx.y;
    if (jt < it) return;
    const int tid = threadIdx.x;
    const int i0 = it * GTT;
    const int j0 = jt * GTT;

    for (int t = tid; t < KDIM * GTT; t += GTHR2) {
        int k = t >> 7, i = t & 127;
        apk[k * GTT + i] = packww(g_uhT[(size_t)k * NROWS + i0 + i]);
    }
    __syncthreads();

    const int tii = (tid >> 4) * 8;     // 16 groups x 8 = 128 i
    const int tjj = (tid & 15) * 8;     // 16 groups x 8 = 128 j
    const float* Bp = g_uhT + (size_t)j0 + tjj;

    unsigned long long acc[8][4];
    #pragma unroll
    for (int i = 0; i < 8; i++)
        #pragma unroll
        for (int c = 0; c < 4; c++) acc[i][c] = 0ull;

    // distance-2 register prefetch, parity-rotated buffers
    ulonglong2 b01[2], b23[2];
    b01[0] = *(const ulonglong2*)(Bp);
    b23[0] = *(const ulonglong2*)(Bp + 4);
    b01[1] = *(const ulonglong2*)(Bp + (size_t)NROWS);
    b23[1] = *(const ulonglong2*)(Bp + (size_t)NROWS + 4);

    #pragma unroll 2
    for (int k = 0; k < KDIM; k++) {
        const int p = k & 1;
        ulonglong2 cb01 = b01[p], cb23 = b23[p];
        if (k + 2 < KDIM) {
            b01[p] = *(const ulonglong2*)(Bp + (size_t)(k + 2) * NROWS);
            b23[p] = *(const ulonglong2*)(Bp + (size_t)(k + 2) * NROWS + 4);
        }
        #pragma unroll
        for (int i = 0; i < 8; i++) {
            unsigned long long a = apk[k * GTT + tii + i];
            asm("fma.rn.f32x2 %0, %1, %2, %0;" : "+l"(acc[i][0]) : "l"(cb01.x), "l"(a));
            asm("fma.rn.f32x2 %0, %1, %2, %0;" : "+l"(acc[i][1]) : "l"(cb01.y), "l"(a));
            asm("fma.rn.f32x2 %0, %1, %2, %0;" : "+l"(acc[i][2]) : "l"(cb23.x), "l"(a));
            asm("fma.rn.f32x2 %0, %1, %2, %0;" : "+l"(acc[i][3]) : "l"(cb23.y), "l"(a));
        }
    }

    // direct store: rows i0+tii.., cols j0+tjj.. (coalesced 32B/thread-row)
    #pragma unroll
    for (int i = 0; i < 8; i++) {
        size_t base = (size_t)(i0 + tii + i) * NROWS + j0 + tjj;
        float4 v1, v2;
        v1.x = u64lo(acc[i][0]); v1.y = u64hi(acc[i][0]);
        v1.z = u64lo(acc[i][1]); v1.w = u64hi(acc[i][1]);
        v2.x = u64lo(acc[i][2]); v2.y = u64hi(acc[i][2]);
        v2.z = u64lo(acc[i][3]); v2.w = u64hi(acc[i][3]);
        __stcs((float4*)(g_inner + base), v1);
        __stcs((float4*)(g_inner + base + 4), v2);
    }

    // transposed store for off-diagonal tiles: D^T at [j0.., i0..]
    if (it != jt) {
        #pragma unroll
        for (int c = 0; c < 8; c++) {
            float col[8];
            #pragma unroll
            for (int i = 0; i < 8; i++)
                col[i] = (c & 1) ? u64hi(acc[i][c >> 1]) : u64lo(acc[i][c >> 1]);
            size_t base = (size_t)(j0 + tjj + c) * NROWS + i0 + tii;
            float4 v1, v2;
            v1.x = col[0]; v1.y = col[1]; v1.z = col[2]; v1.w = col[3];
            v2.x = col[4]; v2.y = col[5]; v2.z = col[6]; v2.w = col[7];
            __stcs((float4*)(g_inner + base), v1);
            __stcs((float4*)(g_inner + base + 4), v2);
        }
    }
}

// ---------------- kernel 3: stats + loss over 8-row slabs --------------------
__global__ void __launch_bounds__(NTHR, 1) stats_loss_kernel() {
    extern __shared__ unsigned char sm[];
    float* rows          = (float*)(sm + SM_ROWS);
    unsigned char* slab  = (unsigned char*)(sm + SM_SLAB);
    unsigned char* simm  = (unsigned char*)(sm + SM_SIMM);
    int*   hist          = (int*)(sm + SM_HIST);
    float* vhist         = (float*)(sm + SM_VHIST);
    float* simv          = (float*)(sm + SM_SIMV);
    int*   scnt          = (int*)(sm + SM_SCNT);
    float* rows8         = (float*)(sm + MISC_ROWS8);
    float* sumS8         = (float*)(sm + MISC_SUMS);
    float* sgt8          = (float*)(sm + MISC_SGT);
    float* vsuf8         = (float*)(sm + MISC_VSUF);
    float* sMin8         = (float*)(sm + MISC_SMIN);
    float* BP8           = (float*)(sm + MISC_BP);
    float* BPd8          = (float*)(sm + MISC_BPD);
    float* lp8           = (float*)(sm + MISC_LP);
    float* ln8           = (float*)(sm + MISC_LN);
    int*   nsim8         = (int*)(sm + MISC_NSIM);
    int*   ksel8         = (int*)(sm + MISC_KSEL);
    int*   kk8           = (int*)(sm + MISC_KK);
    unsigned* pfx8       = (unsigned*)(sm + MISC_PFX);
    int*   ep8           = (int*)(sm + MISC_EP);
    int*   en8           = (int*)(sm + MISC_EN);
    float* wscrF         = (float*)(sm + SM_WSCR);
    int*   wscrI         = (int*)(sm + SM_WSCR);

    const int tid = threadIdx.x;
    const int lane = tid & 31, wid = tid >> 5;
    const int i0  = blockIdx.x * RPB;

    {
        const unsigned rbase = s2u(rows);
        const float* src = g_inner + (size_t)i0 * NROWS;
        #pragma unroll
        for (int i = 0; i < 12; i++) {
            int idx = tid + i * NTHR;
            cpasync16(rbase + (unsigned)idx * 16u, src + (size_t)idx * 4);
        }
        asm volatile("cp.async.commit_group;" ::: "memory");
    }
    for (int t = tid; t < NROWS; t += NTHR) slab[t] = (unsigned char)g_label[t];
    for (int t = tid; t < RPB * 256; t += NTHR) hist[t] = 0;
    if (tid < RPB) scnt[tid] = 0;
    __syncthreads();

    unsigned labr[8];
    #pragma unroll
    for (int r = 0; r < RPB; r++) labr[r] = slab[i0 + r];

    for (int j = tid; j < NROWS; j += NTHR) {
        unsigned lab = slab[j];
        unsigned m = 0;
        #pragma unroll
        for (int r = 0; r < RPB; r++) m |= (lab == labr[r]) ? (1u << r) : 0u;
        simm[j] = (unsigned char)m;
    }
    asm volatile("cp.async.wait_group 0;" ::: "memory");
    __syncthreads();

    {
        float rs[8];
        #pragma unroll
        for (int r = 0; r < 8; r++) {
            unsigned long long a = 0ull;
            const ulonglong2* p = (const ulonglong2*)(rows + r * NROWS);
            for (int t = tid; t < NROWS / 4; t += NTHR) {
                ulonglong2 v = p[t];
                ADD2(a, v.x);
                ADD2(a, v.y);
            }
            rs[r] = u64lo(a) + u64hi(a);
        }
        blockSum8F(rs, wscrF, rows8, tid);
    }

    if (wid < RPB) {
        int r = wid;
        int off = 0;
        for (int it = 0; it < NROWS / 32; it++) {
            int j = it * 32 + lane;
            bool s = (simm[j] >> r) & 1u;
            unsigned bal = __ballot_sync(0xFFFFFFFFu, s);
            if (s) {
                int pos = off + __popc(bal & ((1u << lane) - 1u));
                if (pos < SIMCAP) simv[r * SIMCAP + pos] = rows[r * NROWS + j];
            }
            off += __popc(bal);
        }
        if (lane == 0) scnt[r] = off;
    } else {
        int w = wid - 8;
        int r = w / 3, seg = w % 3;
        int base = seg * 2048;
        for (int it = 0; it < 64; it++) {
            int j = base + it * 32 + lane;
            bool dis = !((simm[j] >> r) & 1u);
            float v = rows[r * NROWS + j];
            if (dis) aggHistAdd(hist, r * 256 + (int)(f2key(v) >> 24));
        }
    }
    __syncthreads();

    if (tid < RPB) {
        int r = tid;
        int ns = scnt[r];
        nsim8[r] = ns;
        int nd = NROWS - ns;
        int ks = nd - (nd * 9) / 10;
        if (ks < 1) ks = 1;
        ksel8[r] = ks;
        kk8[r]   = ks;
        int cnt = ns < SIMCAP ? ns : SIMCAP;
        float* sv = simv + r * SIMCAP;
        float sS = 0.f;
        for (int i = 0; i < cnt; i++) sS += sv[i];
        sumS8[r] = sS;
        int m = ns - (ns * 9) / 10;
        if (m < 1) m = 1;
        float ssum = 0.f;
        for (int it = 0; it < m && it < cnt; it++) {
            int bi = it; float bv = sv[it];
            for (int t2 = it + 1; t2 < cnt; t2++) {
                float x = sv[t2];
                if (x < bv) { bv = x; bi = t2; }
            }
            sv[bi] = sv[it]; sv[it] = bv;
            ssum += bv;
        }
        sMin8[r] = clip64(ssum / (float)(m > 1 ? m : 1));
    }
    __syncthreads();

    if (wid < RPB) {
        int kknext;
        int b0 = radixPick(hist + wid * 256, kk8[wid], lane, &kknext);
        if (lane == 0) { pfx8[wid] = (unsigned)b0; kk8[wid] = kknext; }
    }
    __syncthreads();

    for (int t = tid; t < RPB * 256; t += NTHR) { hist[t] = 0; vhist[t] = 0.f; }
    __syncthreads();

    {
        unsigned p0[8];
        #pragma unroll
        for (int r = 0; r < 8; r++) p0[r] = pfx8[r];
        float sg[8];
        #pragma unroll
        for (int r = 0; r < 8; r++) sg[r] = 0.f;
        for (int j = tid; j < NROWS; j += NTHR) {
            unsigned m = simm[j];
            const float* rj = rows + j;
            #pragma unroll
            for (int r = 0; r < RPB; r++) {
                if (!((m >> r) & 1u)) {
                    float v = rj[r * NROWS];
                    unsigned key = f2key(v);
                    unsigned hi = key >> 24;
                    sg[r] += (hi > p0[r]) ? v : 0.f;
                    if (hi == p0[r]) {
                        int bin = (int)((key >> 16) & 255u);
                        atomicAdd(&hist[r * 256 + bin], 1);
                        atomicAdd(&vhist[r * 256 + bin], v);
                    }
                }
            }
        }
        blockSum8F(sg, wscrF, sgt8, tid);
    }

    if (wid < RPB) {
        int kknext;
        int b1 = radixPick(hist + wid * 256, kk8[wid], lane, &kknext);
        int topbin = 255 - lane * 8;
        float vp = 0.f;
        #pragma unroll
        for (int b = 0; b < 8; b++) {
            int bin = topbin - b;
            if (bin > b1) vp += vhist[wid * 256 + bin];
        }
        #pragma unroll
        for (int o = 16; o > 0; o >>= 1) vp += __shfl_xor_sync(0xFFFFFFFFu, vp, o);
        if (lane == 0) {
            float bm = vhist[wid * 256 + b1] / (float)hist[wid * 256 + b1];
            vsuf8[wid] = vp + (float)kknext * bm;
        }
    }
    __syncthreads();

    if (tid < RPB) {
        int r = tid;
        int ns = nsim8[r], nd = NROWS - ns;
        int ks = ksel8[r];
        float sumD = rows8[r] - sumS8[r];
        float dsum = sgt8[r] + vsuf8[r];
        float dMax = clip64(dsum / (float)(ks > 1 ? ks : 1));
        float meanS  = clip64(sumS8[r] / fmaxf((float)ns, 1.f));
        float meanDS = clip64(sumD / fmaxf((float)nd, 1.f));
        float sMin = sMin8[r];
        BP8[r]  = meanS  - (64.f - meanS) / 64.f * fabsf(meanS - dMax);
        BPd8[r] = meanDS + meanDS / 64.f * fabsf(meanDS - sMin);
    }
    __syncthreads();

    {
        const float C1 = -0.2871949906334119f;  // C_COEF = -ln(99)/16
        const float C2 = 2.f * C1;              // A_COEF * C_COEF (a == 2 exactly)
        float bp[8], bpd[8];
        #pragma unroll
        for (int r = 0; r < 8; r++) { bp[r] = BP8[r]; bpd[r] = BPd8[r]; }
        float lp[8], ln_[8]; int ep[8], en[8];
        #pragma unroll
        for (int r = 0; r < 8; r++) { lp[r] = 0.f; ln_[r] = 0.f; ep[r] = 0; en[r] = 0; }
        for (int j = tid; j < NROWS; j += NTHR) {
            unsigned m = simm[j];
            const float* rj = rows + j;
            #pragma unroll
            for (int r = 0; r < RPB; r++) {
                float v = rj[r * NROWS];
                bool sim = (m >> r) & 1u;
                float th  = sim ? bp[r] : bpd[r];
                float dc  = v - th;
                float cpos = sim ? C1 : -C2;
                float cneg = sim ? C2 : -C1;
                float f = ((dc > 0.f) ? cpos : cneg) * dc;
                float sp = softplus_f(f);
                bool eq = (dc == 0.f);
                if (sim) { if (eq) ep[r]++; else lp[r] += sp; }
                else     { if (eq) en[r]++; else ln_[r] += sp; }
            }
        }
        blockSum8F(lp, wscrF, lp8, tid);
        blockSum8F(ln_, wscrF, ln8, tid);
        blockSum8I(ep, wscrI, ep8, tid);
        blockSum8I(en, wscrI, en8, tid);
    }

    if (tid < RPB) {
        int r = tid;
        int ns = nsim8[r], nd = NROWS - ns;
        int cp = ns - ep8[r];
        int cn = nd - en8[r];
        g_rowpos[i0 + r] = lp8[r] / fmaxf((float)cp, 1.f);
        g_rowneg[i0 + r] = ln8[r] / fmaxf((float)cn, 1.f);
        g_valid[i0 + r]  = (ns > 0 && nd > 0) ? 1 : 0;
    }
}

// ---------------- kernel 4: final scalar -------------------------------------
__global__ void __launch_bounds__(256) final_kernel(float* __restrict__ out) {
    __shared__ float scrF[8];
    __shared__ int scrI[8];
    int tid = threadIdx.x;
    float ps = 0.f, ns = 0.f; int cv = 0;
    for (int i = tid; i < NROWS; i += 256) {
        if (g_valid[i]) { ps += g_rowpos[i]; ns += g_rowneg[i]; cv++; }
    }
    float q = 0.f;
    for (int i = tid; i < QBLKS; i += 256) q += g_qpart[i];
    #pragma unroll
    for (int o = 16; o > 0; o >>= 1) {
        ps += __shfl_xor_sync(0xFFFFFFFFu, ps, o);
        ns += __shfl_xor_sync(0xFFFFFFFFu, ns, o);
        cv += __shfl_xor_sync(0xFFFFFFFFu, cv, o);
        q  += __shfl_xor_sync(0xFFFFFFFFu, q, o);
    }
    if ((tid & 31) == 0) { scrF[tid >> 5] = ps; scrI[tid >> 5] = cv; }
    __syncthreads();
    __shared__ float scrF2[8]; __shared__ float scrF3[8];
    if ((tid & 31) == 0) { scrF2[tid >> 5] = ns; scrF3[tid >> 5] = q; }
    __syncthreads();
    if (tid == 0) {
        float psum = 0.f, nsum = 0.f, qs = 0.f; int cnt = 0;
        for (int w = 0; w < 8; w++) {
            psum += scrF[w]; nsum += scrF2[w]; qs += scrF3[w]; cnt += scrI[w];
        }
        float posL = (cnt > 0) ? psum / fmaxf((float)cnt, 1.f) : 0.f;
        float navL = (cnt > 0) ? nsum / fmaxf((float)cnt, 1.f) : 0.f;
        float ql = 0.1f * qs / (float)(NROWS * KDIM);
        out[0] = posL + navL + ql;
    }
}

extern "C" void kernel_launch(void* const* d_in, const int* in_sizes, int n_in,
                              void* d_out, int out_size) {
    const float* u = (const float*)d_in[0];
    const int*   y = (const int*)d_in[1];
    (void)in_sizes; (void)n_in; (void)out_size;

    cudaFuncSetAttribute(gemm_sym_kernel,
                         cudaFuncAttributeMaxDynamicSharedMemorySize, GSMEM2);
    cudaFuncSetAttribute(stats_loss_kernel,
                         cudaFuncAttributeMaxDynamicSharedMemorySize, SMEM_BYTES);

    tanh_kernel<<<QBLKS, 256>>>(u);
    label_kernel<<<NROWS * 32 / 256, 256>>>(y);
    dim3 ggrid(NROWS / GTT, NROWS / GTT);     // (48, 48), upper triangle active
    gemm_sym_kernel<<<ggrid, GTHR2, GSMEM2>>>();
    stats_loss_kernel<<<NBLK, NTHR, SMEM_BYTES>>>();
    final_kernel<<<1, 256>>>((float*)d_out);
}

// round 11
// speedup vs baseline: 1.4543x; 1.0722x over previous
#include <cuda_runtime.h>
#include <math.h>

#define NROWS 6144
#define KDIM  128
#define NCLS  200
#define RPB   4
#define NBLK  (NROWS / RPB)      // 1536
#define NTHR  512
#define NWARP (NTHR / 32)        // 16
#define SIMCAP 128
#define QBLKS 192

// symmetric GEMM tiling
#define GTT 128
#define GTHR2 256
#define GSMEM2 (KDIM * GTT * 8)  // 131072

// ---- stats kernel shared memory layout (byte offsets) ----
#define SM_ROWS   0                      // [4][6144] f32 = 98304
#define SM_SIMM   98304                  // packed 2 j/byte = 3072
#define SM_HIST   101376                 // [4][256] int = 4096
#define SM_VHIST  105472                 // [4][256] f32 = 4096 (simv aliased here pre-refine)
#define SM_SIMV   SM_VHIST               // [4][128] f32 = 2048 (alias)
#define SM_SCNT   109568                 // 32
#define SM_MISC   109600                 // 512
#define SM_WSCR   110112                 // 512
#define SMEM_BYTES 110624

#define MISC_ROWS4 (SM_MISC + 0)
#define MISC_SUMS  (SM_MISC + 32)
#define MISC_SGT   (SM_MISC + 64)
#define MISC_VSUF  (SM_MISC + 96)
#define MISC_SMIN  (SM_MISC + 128)
#define MISC_BP    (SM_MISC + 160)
#define MISC_BPD   (SM_MISC + 192)
#define MISC_LP    (SM_MISC + 224)
#define MISC_LN    (SM_MISC + 256)
#define MISC_NSIM  (SM_MISC + 288)
#define MISC_KSEL  (SM_MISC + 320)
#define MISC_KK    (SM_MISC + 352)
#define MISC_PFX   (SM_MISC + 384)
#define MISC_EP    (SM_MISC + 416)
#define MISC_EN    (SM_MISC + 448)

static __device__ float g_uhT[KDIM * NROWS];            // transposed tanh(u): [k][j]
static __device__ float g_inner[(size_t)NROWS * NROWS]; // full inner-product matrix
static __device__ int   g_label[NROWS];
static __device__ float g_rowpos[NROWS];
static __device__ float g_rowneg[NROWS];
static __device__ int   g_valid[NROWS];
static __device__ float g_qpart[QBLKS];

__device__ __forceinline__ unsigned f2key(float f) {
    unsigned u = __float_as_uint(f);
    return u ^ ((unsigned)(((int)u) >> 31) | 0x80000000u);
}
__device__ __forceinline__ float clip64(float x) { return fminf(fmaxf(x, 0.f), 64.f); }
__device__ __forceinline__ float softplus_f(float x) {
    return fmaxf(x, 0.f) + __logf(1.f + __expf(-fabsf(x)));
}
__device__ __forceinline__ unsigned long long packww(float w) {
    unsigned long long r;
    asm("mov.b64 %0, {%1, %1};" : "=l"(r) : "f"(w));
    return r;
}
__device__ __forceinline__ unsigned s2u(const void* p) {
    unsigned a;
    asm("{ .reg .u64 t; cvta.to.shared.u64 t, %1; cvt.u32.u64 %0, t; }"
        : "=r"(a) : "l"(p));
    return a;
}
__device__ __forceinline__ void cpasync16(unsigned saddr, const void* g) {
    asm volatile("cp.async.cg.shared.global [%0], [%1], 16;" :: "r"(saddr), "l"(g));
}
#define ADD2(a, b) asm("add.rn.f32x2 %0, %0, %1;" : "+l"(a) : "l"(b))
__device__ __forceinline__ float u64lo(unsigned long long a) {
    return __uint_as_float((unsigned)(a & 0xFFFFFFFFull));
}
__device__ __forceinline__ float u64hi(unsigned long long a) {
    return __uint_as_float((unsigned)(a >> 32));
}
__device__ __forceinline__ void aggHistAdd(int* hist, int idx) {
    unsigned active = __activemask();
    unsigned mask = __match_any_sync(active, idx);
    int leader = __ffs(mask) - 1;
    if ((int)(threadIdx.x & 31) == leader)
        atomicAdd(hist + idx, __popc(mask));
}

// deterministic 4-value block reductions (fixed order)
__device__ __forceinline__ void blockSum4F(float v[4], float* wscr, float* out4, int tid) {
    int lane = tid & 31, wid = tid >> 5;
    #pragma unroll
    for (int r = 0; r < 4; r++) {
        #pragma unroll
        for (int o = 16; o > 0; o >>= 1) v[r] += __shfl_xor_sync(0xFFFFFFFFu, v[r], o);
    }
    if (lane == 0) {
        #pragma unroll
        for (int r = 0; r < 4; r++) wscr[wid * 4 + r] = v[r];
    }
    __syncthreads();
    if (tid < 4) {
        float s = 0.f;
        #pragma unroll
        for (int w = 0; w < NWARP; w++) s += wscr[w * 4 + tid];
        out4[tid] = s;
    }
    __syncthreads();
}
__device__ __forceinline__ void blockSum4I(int v[4], int* wscr, int* out4, int tid) {
    int lane = tid & 31, wid = tid >> 5;
    #pragma unroll
    for (int r = 0; r < 4; r++) {
        #pragma unroll
        for (int o = 16; o > 0; o >>= 1) v[r] += __shfl_xor_sync(0xFFFFFFFFu, v[r], o);
    }
    if (lane == 0) {
        #pragma unroll
        for (int r = 0; r < 4; r++) wscr[wid * 4 + r] = v[r];
    }
    __syncthreads();
    if (tid < 4) {
        int s = 0;
        #pragma unroll
        for (int w = 0; w < NWARP; w++) s += wscr[w * 4 + tid];
        out4[tid] = s;
    }
    __syncthreads();
}

__device__ __forceinline__ int radixPick(const int* histrow, int kk, int lane,
                                         int* kknext_out) {
    int topbin = 255 - lane * 8;
    int csum = 0;
    #pragma unroll
    for (int b = 0; b < 8; b++) csum += histrow[topbin - b];
    int incl = csum;
    #pragma unroll
    for (int o = 1; o < 32; o <<= 1) {
        int t = __shfl_up_sync(0xFFFFFFFFu, incl, o);
        if (lane >= o) incl += t;
    }
    int excl = incl - csum;
    int hit = (excl < kk && kk <= incl) ? 1 : 0;
    unsigned who = __ballot_sync(0xFFFFFFFFu, hit);
    int src = __ffs(who) - 1;
    int bfound = 0, kknext = 0;
    if (hit) {
        int running = excl;
        #pragma unroll
        for (int b = 0; b < 8; b++) {
            int bin = topbin - b;
            int c = histrow[bin];
            running += c;
            if (running >= kk) { bfound = bin; kknext = kk - (running - c); break; }
        }
    }
    bfound = __shfl_sync(0xFFFFFFFFu, bfound, src);
    kknext = __shfl_sync(0xFFFFFFFFu, kknext, src);
    *kknext_out = kknext;
    return bfound;
}

// ---------------- kernel 0: tanh + quantization partials + transpose ----------
__global__ void __launch_bounds__(256) tanh_kernel(const float* __restrict__ u) {
    __shared__ float tile[32][129];
    __shared__ float scr[8];
    const int tid = threadIdx.x;
    const int i0 = blockIdx.x * 32;
    float q = 0.f;
    for (int idx = tid; idx < 32 * KDIM; idx += 256) {
        int r = idx >> 7, k = idx & 127;
        float x = tanhf(u[(i0 + r) * KDIM + k]);
        tile[r][k] = x;
        float s = (x > 0.f) ? 1.f : ((x < 0.f) ? -1.f : 0.f);
        float d = x - s;
        q += d * d;
    }
    __syncthreads();
    for (int idx = tid; idx < 32 * KDIM; idx += 256) {
        int k = idx >> 5, i = idx & 31;
        g_uhT[k * NROWS + i0 + i] = tile[i][k];
    }
    #pragma unroll
    for (int o = 16; o > 0; o >>= 1) q += __shfl_xor_sync(0xFFFFFFFFu, q, o);
    if ((tid & 31) == 0) scr[tid >> 5] = q;
    __syncthreads();
    if (tid == 0) {
        float s = 0.f;
        for (int w = 0; w < 8; w++) s += scr[w];
        g_qpart[blockIdx.x] = s;
    }
}

// ---------------- kernel 1: one-hot -> label (warp per row) ------------------
__global__ void __launch_bounds__(256) label_kernel(const int* __restrict__ y) {
    int w = (blockIdx.x * blockDim.x + threadIdx.x) >> 5;
    int lane = threadIdx.x & 31;
    if (w < NROWS) {
        const int* yr = y + (size_t)w * NCLS;
        int lab = 0;
        for (int c = lane; c < NCLS; c += 32)
            if (yr[c] != 0) lab = c;
        #pragma unroll
        for (int o = 16; o > 0; o >>= 1)
            lab = max(lab, __shfl_xor_sync(0xFFFFFFFFu, lab, o));
        if (lane == 0) g_label[w] = lab;
    }
}

// ---------------- kernel 2: SYMMETRIC GEMM inner = uh @ uh^T -----------------
__global__ void __launch_bounds__(GTHR2, 1) gemm_sym_kernel() {
    extern __shared__ unsigned long long apk[];   // [KDIM][GTT] (a,a)-packed
    const int it = blockIdx.x, jt = blockIdx.y;
    if (jt < it) return;
    const int tid = threadIdx.x;
    const int i0 = it * GTT;
    const int j0 = jt * GTT;

    for (int t = tid; t < KDIM * GTT; t += GTHR2) {
        int k = t >> 7, i = t & 127;
        apk[k * GTT + i] = packww(g_uhT[(size_t)k * NROWS + i0 + i]);
    }
    __syncthreads();

    const int tii = (tid >> 4) * 8;
    const int tjj = (tid & 15) * 8;
    const float* Bp = g_uhT + (size_t)j0 + tjj;

    unsigned long long acc[8][4];
    #pragma unroll
    for (int i = 0; i < 8; i++)
        #pragma unroll
        for (int c = 0; c < 4; c++) acc[i][c] = 0ull;

    ulonglong2 b01[2], b23[2];
    b01[0] = *(const ulonglong2*)(Bp);
    b23[0] = *(const ulonglong2*)(Bp + 4);
    b01[1] = *(const ulonglong2*)(Bp + (size_t)NROWS);
    b23[1] = *(const ulonglong2*)(Bp + (size_t)NROWS + 4);

    #pragma unroll 2
    for (int k = 0; k < KDIM; k++) {
        const int p = k & 1;
        ulonglong2 cb01 = b01[p], cb23 = b23[p];
        if (k + 2 < KDIM) {
            b01[p] = *(const ulonglong2*)(Bp + (size_t)(k + 2) * NROWS);
            b23[p] = *(const ulonglong2*)(Bp + (size_t)(k + 2) * NROWS + 4);
        }
        // A values: 4x LDS.128 (pairs) instead of 8x LDS.64
        const ulonglong2* ap2 = (const ulonglong2*)(apk + k * GTT + tii);
        ulonglong2 ap[4];
        ap[0] = ap2[0]; ap[1] = ap2[1]; ap[2] = ap2[2]; ap[3] = ap2[3];
        unsigned long long a[8];
        #pragma unroll
        for (int h = 0; h < 4; h++) { a[2 * h] = ap[h].x; a[2 * h + 1] = ap[h].y; }
        #pragma unroll
        for (int i = 0; i < 8; i++) {
            asm("fma.rn.f32x2 %0, %1, %2, %0;" : "+l"(acc[i][0]) : "l"(cb01.x), "l"(a[i]));
            asm("fma.rn.f32x2 %0, %1, %2, %0;" : "+l"(acc[i][1]) : "l"(cb01.y), "l"(a[i]));
            asm("fma.rn.f32x2 %0, %1, %2, %0;" : "+l"(acc[i][2]) : "l"(cb23.x), "l"(a[i]));
            asm("fma.rn.f32x2 %0, %1, %2, %0;" : "+l"(acc[i][3]) : "l"(cb23.y), "l"(a[i]));
        }
    }

    #pragma unroll
    for (int i = 0; i < 8; i++) {
        size_t base = (size_t)(i0 + tii + i) * NROWS + j0 + tjj;
        float4 v1, v2;
        v1.x = u64lo(acc[i][0]); v1.y = u64hi(acc[i][0]);
        v1.z = u64lo(acc[i][1]); v1.w = u64hi(acc[i][1]);
        v2.x = u64lo(acc[i][2]); v2.y = u64hi(acc[i][2]);
        v2.z = u64lo(acc[i][3]); v2.w = u64hi(acc[i][3]);
        __stcs((float4*)(g_inner + base), v1);
        __stcs((float4*)(g_inner + base + 4), v2);
    }

    if (it != jt) {
        #pragma unroll
        for (int c = 0; c < 8; c++) {
            float col[8];
            #pragma unroll
            for (int i = 0; i < 8; i++)
                col[i] = (c & 1) ? u64hi(acc[i][c >> 1]) : u64lo(acc[i][c >> 1]);
            size_t base = (size_t)(j0 + tjj + c) * NROWS + i0 + tii;
            float4 v1, v2;
            v1.x = col[0]; v1.y = col[1]; v1.z = col[2]; v1.w = col[3];
            v2.x = col[4]; v2.y = col[5]; v2.z = col[6]; v2.w = col[7];
            __stcs((float4*)(g_inner + base), v1);
            __stcs((float4*)(g_inner + base + 4), v2);
        }
    }
}

// ---------------- kernel 3: stats + loss over 4-row slabs (2 CTAs/SM) --------
__global__ void __launch_bounds__(NTHR, 2) stats_loss_kernel() {
    extern __shared__ unsigned char sm[];
    float* rows          = (float*)(sm + SM_ROWS);
    unsigned char* simm  = (unsigned char*)(sm + SM_SIMM);   // packed 2 j / byte
    int*   hist          = (int*)(sm + SM_HIST);
    float* vhist         = (float*)(sm + SM_VHIST);
    float* simv          = (float*)(sm + SM_SIMV);           // alias of vhist
    int*   scnt          = (int*)(sm + SM_SCNT);
    float* rows4         = (float*)(sm + MISC_ROWS4);
    float* sumS4         = (float*)(sm + MISC_SUMS);
    float* sgt4          = (float*)(sm + MISC_SGT);
    float* vsuf4         = (float*)(sm + MISC_VSUF);
    float* sMin4         = (float*)(sm + MISC_SMIN);
    float* BP4           = (float*)(sm + MISC_BP);
    float* BPd4          = (float*)(sm + MISC_BPD);
    float* lp4           = (float*)(sm + MISC_LP);
    float* ln4           = (float*)(sm + MISC_LN);
    int*   nsim4         = (int*)(sm + MISC_NSIM);
    int*   ksel4         = (int*)(sm + MISC_KSEL);
    int*   kk4           = (int*)(sm + MISC_KK);
    unsigned* pfx4       = (unsigned*)(sm + MISC_PFX);
    int*   ep4           = (int*)(sm + MISC_EP);
    int*   en4           = (int*)(sm + MISC_EN);
    float* wscrF         = (float*)(sm + SM_WSCR);
    int*   wscrI         = (int*)(sm + SM_WSCR);

    const int tid = threadIdx.x;
    const int lane = tid & 31, wid = tid >> 5;
    const int i0  = blockIdx.x * RPB;

    // ---- async slab load (96 KB), overlapped with mask build ----
    {
        const unsigned rbase = s2u(rows);
        const float* src = g_inner + (size_t)i0 * NROWS;
        #pragma unroll
        for (int i = 0; i < 12; i++) {
            int idx = tid + i * NTHR;
            cpasync16(rbase + (unsigned)idx * 16u, src + (size_t)idx * 4);
        }
        asm volatile("cp.async.commit_group;" ::: "memory");
    }
    int labr[RPB];
    #pragma unroll
    for (int r = 0; r < RPB; r++) labr[r] = g_label[i0 + r];
    // packed mask build: one byte covers j=2b, 2b+1
    for (int b = tid; b < NROWS / 2; b += NTHR) {
        int l0 = g_label[2 * b], l1 = g_label[2 * b + 1];
        unsigned m = 0;
        #pragma unroll
        for (int r = 0; r < RPB; r++) {
            m |= (l0 == labr[r]) ? (1u << r) : 0u;
            m |= (l1 == labr[r]) ? (1u << (4 + r)) : 0u;
        }
        simm[b] = (unsigned char)m;
    }
    for (int t = tid; t < RPB * 256; t += NTHR) hist[t] = 0;
    if (tid < RPB) scnt[tid] = 0;
    asm volatile("cp.async.wait_group 0;" ::: "memory");
    __syncthreads();

    // ---- rowsum sweep (mask-free, packed f32x2) ----
    {
        float rs[4];
        #pragma unroll
        for (int r = 0; r < 4; r++) {
            unsigned long long a = 0ull;
            const ulonglong2* p = (const ulonglong2*)(rows + r * NROWS);
            for (int t = tid; t < NROWS / 4; t += NTHR) {
                ulonglong2 v = p[t];
                ADD2(a, v.x);
                ADD2(a, v.y);
            }
            rs[r] = u64lo(a) + u64hi(a);
        }
        blockSum4F(rs, wscrF, rows4, tid);
    }

    // ---- pass-0: warps 0-3 collect similars | warps 4-15 build count hist ----
    if (wid < RPB) {
        int r = wid;
        int off = 0;
        for (int it = 0; it < NROWS / 32; it++) {
            int j = it * 32 + lane;
            bool s = (simm[j >> 1] >> ((lane & 1) * 4 + r)) & 1u;
            unsigned bal = __ballot_sync(0xFFFFFFFFu, s);
            if (s) {
                int pos = off + __popc(bal & ((1u << lane) - 1u));
                if (pos < SIMCAP) simv[r * SIMCAP + pos] = rows[r * NROWS + j];
            }
            off += __popc(bal);
        }
        if (lane == 0) scnt[r] = off;
    } else {
        int w = wid - 4;              // 0..11
        int r = w / 3, seg = w % 3;   // 3 segs x 2048
        int base = seg * 2048;
        for (int it = 0; it < 64; it++) {
            int j = base + it * 32 + lane;
            bool dis = !((simm[j >> 1] >> ((lane & 1) * 4 + r)) & 1u);
            float v = rows[r * NROWS + j];
            if (dis) aggHistAdd(hist, r * 256 + (int)(f2key(v) >> 24));
        }
    }
    __syncthreads();

    // ---- sumS + sMin + radix init (threads 0..3) ----
    if (tid < RPB) {
        int r = tid;
        int ns = scnt[r];
        nsim4[r] = ns;
        int nd = NROWS - ns;
        int ks = nd - (nd * 9) / 10;
        if (ks < 1) ks = 1;
        ksel4[r] = ks;
        kk4[r]   = ks;
        int cnt = ns < SIMCAP ? ns : SIMCAP;
        float* sv = simv + r * SIMCAP;
        float sS = 0.f;
        for (int i = 0; i < cnt; i++) sS += sv[i];
        sumS4[r] = sS;
        int m = ns - (ns * 9) / 10;
        if (m < 1) m = 1;
        float ssum = 0.f;
        for (int it = 0; it < m && it < cnt; it++) {
            int bi = it; float bv = sv[it];
            for (int t2 = it + 1; t2 < cnt; t2++) {
                float x = sv[t2];
                if (x < bv) { bv = x; bi = t2; }
            }
            sv[bi] = sv[it]; sv[it] = bv;
            ssum += bv;
        }
        sMin4[r] = clip64(ssum / (float)(m > 1 ? m : 1));
    }
    __syncthreads();

    // ---- radix pass-0 pick (warps 0..3) ----
    if (wid < RPB) {
        int kknext;
        int b0 = radixPick(hist + wid * 256, kk4[wid], lane, &kknext);
        if (lane == 0) { pfx4[wid] = (unsigned)b0; kk4[wid] = kknext; }
    }
    __syncthreads();

    // zero hists for refine (this also wipes simv — no longer needed)
    for (int t = tid; t < RPB * 256; t += NTHR) { hist[t] = 0; vhist[t] = 0.f; }
    __syncthreads();

    // ---- refine sweep: sum above byte-0 bin, 16-bit hist inside bin ----
    {
        unsigned p0[4];
        #pragma unroll
        for (int r = 0; r < 4; r++) p0[r] = pfx4[r];
        float sg[4];
        #pragma unroll
        for (int r = 0; r < 4; r++) sg[r] = 0.f;
        const int sh = (tid & 1) * 4;
        for (int j = tid; j < NROWS; j += NTHR) {
            unsigned m = (simm[j >> 1] >> sh) & 0xFu;
            const float* rj = rows + j;
            #pragma unroll
            for (int r = 0; r < RPB; r++) {
                if (!((m >> r) & 1u)) {
                    float v = rj[r * NROWS];
                    unsigned key = f2key(v);
                    unsigned hi = key >> 24;
                    sg[r] += (hi > p0[r]) ? v : 0.f;
                    if (hi == p0[r]) {
                        int bin = (int)((key >> 16) & 255u);
                        atomicAdd(&hist[r * 256 + bin], 1);
                        atomicAdd(&vhist[r * 256 + bin], v);
                    }
                }
            }
        }
        blockSum4F(sg, wscrF, sgt4, tid);
    }

    // ---- pick1 + suffix value sum (warps 0..3) ----
    if (wid < RPB) {
        int kknext;
        int b1 = radixPick(hist + wid * 256, kk4[wid], lane, &kknext);
        int topbin = 255 - lane * 8;
        float vp = 0.f;
        #pragma unroll
        for (int b = 0; b < 8; b++) {
            int bin = topbin - b;
            if (bin > b1) vp += vhist[wid * 256 + bin];
        }
        #pragma unroll
        for (int o = 16; o > 0; o >>= 1) vp += __shfl_xor_sync(0xFFFFFFFFu, vp, o);
        if (lane == 0) {
            float bm = vhist[wid * 256 + b1] / (float)hist[wid * 256 + b1];
            vsuf4[wid] = vp + (float)kknext * bm;
        }
    }
    __syncthreads();

    // ---- thresholds BP/BPd ----
    if (tid < RPB) {
        int r = tid;
        int ns = nsim4[r], nd = NROWS - ns;
        int ks = ksel4[r];
        float sumD = rows4[r] - sumS4[r];
        float dsum = sgt4[r] + vsuf4[r];
        float dMax = clip64(dsum / (float)(ks > 1 ? ks : 1));
        float meanS  = clip64(sumS4[r] / fmaxf((float)ns, 1.f));
        float meanDS = clip64(sumD / fmaxf((float)nd, 1.f));
        float sMin = sMin4[r];
        BP4[r]  = meanS  - (64.f - meanS) / 64.f * fabsf(meanS - dMax);
        BPd4[r] = meanDS + meanDS / 64.f * fabsf(meanDS - sMin);
    }
    __syncthreads();

    // ---- loss sweep ----
    {
        const float C1 = -0.2871949906334119f;  // C_COEF = -ln(99)/16
        const float C2 = 2.f * C1;              // A_COEF * C_COEF (a == 2 exactly)
        float bp[4], bpd[4];
        #pragma unroll
        for (int r = 0; r < 4; r++) { bp[r] = BP4[r]; bpd[r] = BPd4[r]; }
        float lp[4], ln_[4]; int ep[4], en[4];
        #pragma unroll
        for (int r = 0; r < 4; r++) { lp[r] = 0.f; ln_[r] = 0.f; ep[r] = 0; en[r] = 0; }
        const int sh = (tid & 1) * 4;
        for (int j = tid; j < NROWS; j += NTHR) {
            unsigned m = (simm[j >> 1] >> sh) & 0xFu;
            const float* rj = rows + j;
            #pragma unroll
            for (int r = 0; r < RPB; r++) {
                float v = rj[r * NROWS];
                bool sim = (m >> r) & 1u;
                float th  = sim ? bp[r] : bpd[r];
                float dc  = v - th;
                float cpos = sim ? C1 : -C2;
                float cneg = sim ? C2 : -C1;
                float f = ((dc > 0.f) ? cpos : cneg) * dc;
                float sp = softplus_f(f);
                bool eq = (dc == 0.f);
                if (sim) { if (eq) ep[r]++; else lp[r] += sp; }
                else     { if (eq) en[r]++; else ln_[r] += sp; }
            }
        }
        blockSum4F(lp, wscrF, lp4, tid);
        blockSum4F(ln_, wscrF, ln4, tid);
        blockSum4I(ep, wscrI, ep4, tid);
        blockSum4I(en, wscrI, en4, tid);
    }

    if (tid < RPB) {
        int r = tid;
        int ns = nsim4[r], nd = NROWS - ns;
        int cp = ns - ep4[r];
        int cn = nd - en4[r];
        g_rowpos[i0 + r] = lp4[r] / fmaxf((float)cp, 1.f);
        g_rowneg[i0 + r] = ln4[r] / fmaxf((float)cn, 1.f);
        g_valid[i0 + r]  = (ns > 0 && nd > 0) ? 1 : 0;
    }
}

// ---------------- kernel 4: final scalar -------------------------------------
__global__ void __launch_bounds__(256) final_kernel(float* __restrict__ out) {
    __shared__ float scrF[8];
    __shared__ int scrI[8];
    int tid = threadIdx.x;
    float ps = 0.f, ns = 0.f; int cv = 0;
    for (int i = tid; i < NROWS; i += 256) {
        if (g_valid[i]) { ps += g_rowpos[i]; ns += g_rowneg[i]; cv++; }
    }
    float q = 0.f;
    for (int i = tid; i < QBLKS; i += 256) q += g_qpart[i];
    #pragma unroll
    for (int o = 16; o > 0; o >>= 1) {
        ps += __shfl_xor_sync(0xFFFFFFFFu, ps, o);
        ns += __shfl_xor_sync(0xFFFFFFFFu, ns, o);
        cv += __shfl_xor_sync(0xFFFFFFFFu, cv, o);
        q  += __shfl_xor_sync(0xFFFFFFFFu, q, o);
    }
    if ((tid & 31) == 0) { scrF[tid >> 5] = ps; scrI[tid >> 5] = cv; }
    __syncthreads();
    __shared__ float scrF2[8]; __shared__ float scrF3[8];
    if ((tid & 31) == 0) { scrF2[tid >> 5] = ns; scrF3[tid >> 5] = q; }
    __syncthreads();
    if (tid == 0) {
        float psum = 0.f, nsum = 0.f, qs = 0.f; int cnt = 0;
        for (int w = 0; w < 8; w++) {
            psum += scrF[w]; nsum += scrF2[w]; qs += scrF3[w]; cnt += scrI[w];
        }
        float posL = (cnt > 0) ? psum / fmaxf((float)cnt, 1.f) : 0.f;
        float navL = (cnt > 0) ? nsum / fmaxf((float)cnt, 1.f) : 0.f;
        float ql = 0.1f * qs / (float)(NROWS * KDIM);
        out[0] = posL + navL + ql;
    }
}

extern "C" void kernel_launch(void* const* d_in, const int* in_sizes, int n_in,
                              void* d_out, int out_size) {
    const float* u = (const float*)d_in[0];
    const int*   y = (const int*)d_in[1];
    (void)in_sizes; (void)n_in; (void)out_size;

    cudaFuncSetAttribute(gemm_sym_kernel,
                         cudaFuncAttributeMaxDynamicSharedMemorySize, GSMEM2);
    cudaFuncSetAttribute(stats_loss_kernel,
                         cudaFuncAttributeMaxDynamicSharedMemorySize, SMEM_BYTES);

    tanh_kernel<<<QBLKS, 256>>>(u);
    label_kernel<<<NROWS * 32 / 256, 256>>>(y);
    dim3 ggrid(NROWS / GTT, NROWS / GTT);     // (48, 48), upper triangle active
    gemm_sym_kernel<<<ggrid, GTHR2, GSMEM2>>>();
    stats_loss_kernel<<<NBLK, NTHR, SMEM_BYTES>>>();
    final_kernel<<<1, 256>>>((float*)d_out);
}

// round 12
// speedup vs baseline: 1.5690x; 1.0789x over previous
#include <cuda_runtime.h>
#include <math.h>

#define NROWS 6144
#define KDIM  128
#define NCLS  200
#define RPB   2
#define NBLK  (NROWS / RPB)      // 3072
#define NTHR  512
#define NWARP (NTHR / 32)        // 16
#define SIMCAP 128
#define QBLKS 192

// symmetric GEMM tiling
#define GTT 128
#define GTHR2 256
#define GSMEM2 (KDIM * GTT * 8)  // 131072

// ---- stats kernel shared memory layout (byte offsets) ----
#define SM_ROWS   0                      // [2][6144] f32 = 49152
#define SM_SIMM   49152                  // packed 4 j/byte (2 bits/j) = 1536
#define SM_HIST   50688                  // [2][256] int = 2048
#define SM_VHIST  52736                  // [2][256] f32 = 2048 (simv aliased pre-refine)
#define SM_SIMV   SM_VHIST               // [2][128] f32 = 1024 (alias)
#define SM_SCNT   54784                  // 32
#define SM_MISC   54816                  // 384
#define SM_WSCR   55200                  // 128
#define SMEM_BYTES 55328

#define MISC_SUMS  (SM_MISC + 0)
#define MISC_SGT   (SM_MISC + 16)
#define MISC_VSUF  (SM_MISC + 32)
#define MISC_SMIN  (SM_MISC + 48)
#define MISC_BP    (SM_MISC + 64)
#define MISC_BPD   (SM_MISC + 80)
#define MISC_LP    (SM_MISC + 96)
#define MISC_LN    (SM_MISC + 112)
#define MISC_NSIM  (SM_MISC + 128)
#define MISC_KSEL  (SM_MISC + 144)
#define MISC_KK    (SM_MISC + 160)
#define MISC_PFX   (SM_MISC + 176)
#define MISC_EP    (SM_MISC + 192)
#define MISC_EN    (SM_MISC + 208)

static __device__ float g_uhT[KDIM * NROWS];            // transposed tanh(u): [k][j]
static __device__ float g_inner[(size_t)NROWS * NROWS]; // full inner-product matrix
static __device__ float g_colsum[KDIM];                 // sum over j of uhT[k][j]
static __device__ float g_rowsum[NROWS];                // uh_i . colsum
static __device__ int   g_label[NROWS];
static __device__ float g_rowpos[NROWS];
static __device__ float g_rowneg[NROWS];
static __device__ int   g_valid[NROWS];
static __device__ float g_qpart[QBLKS];

__device__ __forceinline__ unsigned f2key(float f) {
    unsigned u = __float_as_uint(f);
    return u ^ ((unsigned)(((int)u) >> 31) | 0x80000000u);
}
__device__ __forceinline__ float clip64(float x) { return fminf(fmaxf(x, 0.f), 64.f); }
__device__ __forceinline__ float softplus_f(float x) {
    return fmaxf(x, 0.f) + __logf(1.f + __expf(-fabsf(x)));
}
__device__ __forceinline__ unsigned long long packww(float w) {
    unsigned long long r;
    asm("mov.b64 %0, {%1, %1};" : "=l"(r) : "f"(w));
    return r;
}
__device__ __forceinline__ unsigned s2u(const void* p) {
    unsigned a;
    asm("{ .reg .u64 t; cvta.to.shared.u64 t, %1; cvt.u32.u64 %0, t; }"
        : "=r"(a) : "l"(p));
    return a;
}
__device__ __forceinline__ void cpasync16(unsigned saddr, const void* g) {
    asm volatile("cp.async.cg.shared.global [%0], [%1], 16;" :: "r"(saddr), "l"(g));
}
__device__ __forceinline__ float u64lo(unsigned long long a) {
    return __uint_as_float((unsigned)(a & 0xFFFFFFFFull));
}
__device__ __forceinline__ float u64hi(unsigned long long a) {
    return __uint_as_float((unsigned)(a >> 32));
}
__device__ __forceinline__ void aggHistAdd(int* hist, int idx) {
    unsigned active = __activemask();
    unsigned mask = __match_any_sync(active, idx);
    int leader = __ffs(mask) - 1;
    if ((int)(threadIdx.x & 31) == leader)
        atomicAdd(hist + idx, __popc(mask));
}

// deterministic 2-value block reductions (fixed order)
__device__ __forceinline__ void blockSum2F(float v[2], float* wscr, float* out2, int tid) {
    int lane = tid & 31, wid = tid >> 5;
    #pragma unroll
    for (int r = 0; r < 2; r++) {
        #pragma unroll
        for (int o = 16; o > 0; o >>= 1) v[r] += __shfl_xor_sync(0xFFFFFFFFu, v[r], o);
    }
    if (lane == 0) {
        wscr[wid * 2] = v[0];
        wscr[wid * 2 + 1] = v[1];
    }
    __syncthreads();
    if (tid < 2) {
        float s = 0.f;
        #pragma unroll
        for (int w = 0; w < NWARP; w++) s += wscr[w * 2 + tid];
        out2[tid] = s;
    }
    __syncthreads();
}
__device__ __forceinline__ void blockSum2I(int v[2], int* wscr, int* out2, int tid) {
    int lane = tid & 31, wid = tid >> 5;
    #pragma unroll
    for (int r = 0; r < 2; r++) {
        #pragma unroll
        for (int o = 16; o > 0; o >>= 1) v[r] += __shfl_xor_sync(0xFFFFFFFFu, v[r], o);
    }
    if (lane == 0) {
        wscr[wid * 2] = v[0];
        wscr[wid * 2 + 1] = v[1];
    }
    __syncthreads();
    if (tid < 2) {
        int s = 0;
        #pragma unroll
        for (int w = 0; w < NWARP; w++) s += wscr[w * 2 + tid];
        out2[tid] = s;
    }
    __syncthreads();
}

__device__ __forceinline__ int radixPick(const int* histrow, int kk, int lane,
                                         int* kknext_out) {
    int topbin = 255 - lane * 8;
    int csum = 0;
    #pragma unroll
    for (int b = 0; b < 8; b++) csum += histrow[topbin - b];
    int incl = csum;
    #pragma unroll
    for (int o = 1; o < 32; o <<= 1) {
        int t = __shfl_up_sync(0xFFFFFFFFu, incl, o);
        if (lane >= o) incl += t;
    }
    int excl = incl - csum;
    int hit = (excl < kk && kk <= incl) ? 1 : 0;
    unsigned who = __ballot_sync(0xFFFFFFFFu, hit);
    int src = __ffs(who) - 1;
    int bfound = 0, kknext = 0;
    if (hit) {
        int running = excl;
        #pragma unroll
        for (int b = 0; b < 8; b++) {
            int bin = topbin - b;
            int c = histrow[bin];
            running += c;
            if (running >= kk) { bfound = bin; kknext = kk - (running - c); break; }
        }
    }
    bfound = __shfl_sync(0xFFFFFFFFu, bfound, src);
    kknext = __shfl_sync(0xFFFFFFFFu, kknext, src);
    *kknext_out = kknext;
    return bfound;
}

// ---------------- kernel 0: tanh + quantization partials + transpose ----------
__global__ void __launch_bounds__(256) tanh_kernel(const float* __restrict__ u) {
    __shared__ float tile[32][129];
    __shared__ float scr[8];
    const int tid = threadIdx.x;
    const int i0 = blockIdx.x * 32;
    float q = 0.f;
    for (int idx = tid; idx < 32 * KDIM; idx += 256) {
        int r = idx >> 7, k = idx & 127;
        float x = tanhf(u[(i0 + r) * KDIM + k]);
        tile[r][k] = x;
        float s = (x > 0.f) ? 1.f : ((x < 0.f) ? -1.f : 0.f);
        float d = x - s;
        q += d * d;
    }
    __syncthreads();
    for (int idx = tid; idx < 32 * KDIM; idx += 256) {
        int k = idx >> 5, i = idx & 31;
        g_uhT[k * NROWS + i0 + i] = tile[i][k];
    }
    #pragma unroll
    for (int o = 16; o > 0; o >>= 1) q += __shfl_xor_sync(0xFFFFFFFFu, q, o);
    if ((tid & 31) == 0) scr[tid >> 5] = q;
    __syncthreads();
    if (tid == 0) {
        float s = 0.f;
        for (int w = 0; w < 8; w++) s += scr[w];
        g_qpart[blockIdx.x] = s;
    }
}

// ---------------- kernel 1: one-hot -> label (warp per row) ------------------
__global__ void __launch_bounds__(256) label_kernel(const int* __restrict__ y) {
    int w = (blockIdx.x * blockDim.x + threadIdx.x) >> 5;
    int lane = threadIdx.x & 31;
    if (w < NROWS) {
        const int* yr = y + (size_t)w * NCLS;
        int lab = 0;
        for (int c = lane; c < NCLS; c += 32)
            if (yr[c] != 0) lab = c;
        #pragma unroll
        for (int o = 16; o > 0; o >>= 1)
            lab = max(lab, __shfl_xor_sync(0xFFFFFFFFu, lab, o));
        if (lane == 0) g_label[w] = lab;
    }
}

// ---------------- kernel 1b: colsum[k] = sum_j uhT[k][j] ---------------------
__global__ void __launch_bounds__(256) colsum_kernel() {
    __shared__ float scr[8];
    const int k = blockIdx.x;
    const int tid = threadIdx.x;
    const float4* p = (const float4*)(g_uhT + (size_t)k * NROWS);
    float a = 0.f;
    for (int t = tid; t < NROWS / 4; t += 256) {
        float4 v = p[t];
        a += (v.x + v.y) + (v.z + v.w);
    }
    #pragma unroll
    for (int o = 16; o > 0; o >>= 1) a += __shfl_xor_sync(0xFFFFFFFFu, a, o);
    if ((tid & 31) == 0) scr[tid >> 5] = a;
    __syncthreads();
    if (tid == 0) {
        float s = 0.f;
        for (int w = 0; w < 8; w++) s += scr[w];
        g_colsum[k] = s;
    }
}

// ---------------- kernel 1c: rowsum[i] = uh_i . colsum -----------------------
__global__ void __launch_bounds__(256) rowsum_kernel() {
    __shared__ float cs[KDIM];
    const int tid = threadIdx.x;
    if (tid < KDIM) cs[tid] = g_colsum[tid];
    __syncthreads();
    int i = blockIdx.x * 256 + tid;
    float acc = 0.f;
    #pragma unroll 8
    for (int k = 0; k < KDIM; k++)
        acc += g_uhT[(size_t)k * NROWS + i] * cs[k];
    g_rowsum[i] = acc;
}

// ---------------- kernel 2: SYMMETRIC GEMM inner = uh @ uh^T -----------------
__global__ void __launch_bounds__(GTHR2, 1) gemm_sym_kernel() {
    extern __shared__ unsigned long long apk[];   // [KDIM][GTT] (a,a)-packed
    const int it = blockIdx.x, jt = blockIdx.y;
    if (jt < it) return;
    const int tid = threadIdx.x;
    const int i0 = it * GTT;
    const int j0 = jt * GTT;

    for (int t = tid; t < KDIM * GTT; t += GTHR2) {
        int k = t >> 7, i = t & 127;
        apk[k * GTT + i] = packww(g_uhT[(size_t)k * NROWS + i0 + i]);
    }
    __syncthreads();

    const int tii = (tid >> 4) * 8;
    const int tjj = (tid & 15) * 8;
    const float* Bp = g_uhT + (size_t)j0 + tjj;

    unsigned long long acc[8][4];
    #pragma unroll
    for (int i = 0; i < 8; i++)
        #pragma unroll
        for (int c = 0; c < 4; c++) acc[i][c] = 0ull;

    ulonglong2 b01[2], b23[2];
    b01[0] = *(const ulonglong2*)(Bp);
    b23[0] = *(const ulonglong2*)(Bp + 4);
    b01[1] = *(const ulonglong2*)(Bp + (size_t)NROWS);
    b23[1] = *(const ulonglong2*)(Bp + (size_t)NROWS + 4);

    #pragma unroll 2
    for (int k = 0; k < KDIM; k++) {
        const int p = k & 1;
        ulonglong2 cb01 = b01[p], cb23 = b23[p];
        if (k + 2 < KDIM) {
            b01[p] = *(const ulonglong2*)(Bp + (size_t)(k + 2) * NROWS);
            b23[p] = *(const ulonglong2*)(Bp + (size_t)(k + 2) * NROWS + 4);
        }
        const ulonglong2* ap2 = (const ulonglong2*)(apk + k * GTT + tii);
        ulonglong2 ap[4];
        ap[0] = ap2[0]; ap[1] = ap2[1]; ap[2] = ap2[2]; ap[3] = ap2[3];
        unsigned long long a[8];
        #pragma unroll
        for (int h = 0; h < 4; h++) { a[2 * h] = ap[h].x; a[2 * h + 1] = ap[h].y; }
        #pragma unroll
        for (int i = 0; i < 8; i++) {
            asm("fma.rn.f32x2 %0, %1, %2, %0;" : "+l"(acc[i][0]) : "l"(cb01.x), "l"(a[i]));
            asm("fma.rn.f32x2 %0, %1, %2, %0;" : "+l"(acc[i][1]) : "l"(cb01.y), "l"(a[i]));
            asm("fma.rn.f32x2 %0, %1, %2, %0;" : "+l"(acc[i][2]) : "l"(cb23.x), "l"(a[i]));
            asm("fma.rn.f32x2 %0, %1, %2, %0;" : "+l"(acc[i][3]) : "l"(cb23.y), "l"(a[i]));
        }
    }

    #pragma unroll
    for (int i = 0; i < 8; i++) {
        size_t base = (size_t)(i0 + tii + i) * NROWS + j0 + tjj;
        float4 v1, v2;
        v1.x = u64lo(acc[i][0]); v1.y = u64hi(acc[i][0]);
        v1.z = u64lo(acc[i][1]); v1.w = u64hi(acc[i][1]);
        v2.x = u64lo(acc[i][2]); v2.y = u64hi(acc[i][2]);
        v2.z = u64lo(acc[i][3]); v2.w = u64hi(acc[i][3]);
        __stcs((float4*)(g_inner + base), v1);
        __stcs((float4*)(g_inner + base + 4), v2);
    }

    if (it != jt) {
        #pragma unroll
        for (int c = 0; c < 8; c++) {
            float col[8];
            #pragma unroll
            for (int i = 0; i < 8; i++)
                col[i] = (c & 1) ? u64hi(acc[i][c >> 1]) : u64lo(acc[i][c >> 1]);
            size_t base = (size_t)(j0 + tjj + c) * NROWS + i0 + tii;
            float4 v1, v2;
            v1.x = col[0]; v1.y = col[1]; v1.z = col[2]; v1.w = col[3];
            v2.x = col[4]; v2.y = col[5]; v2.z = col[6]; v2.w = col[7];
            __stcs((float4*)(g_inner + base), v1);
            __stcs((float4*)(g_inner + base + 4), v2);
        }
    }
}

// ---------------- kernel 3: stats + loss over 2-row slabs (4 CTAs/SM) --------
__global__ void __launch_bounds__(NTHR, 4) stats_loss_kernel() {
    extern __shared__ unsigned char sm[];
    float* rows          = (float*)(sm + SM_ROWS);
    unsigned char* simm  = (unsigned char*)(sm + SM_SIMM);   // 2 bits/j, 4 j/byte
    int*   hist          = (int*)(sm + SM_HIST);
    float* vhist         = (float*)(sm + SM_VHIST);
    float* simv          = (float*)(sm + SM_SIMV);           // alias of vhist
    int*   scnt          = (int*)(sm + SM_SCNT);
    float* sumS2         = (float*)(sm + MISC_SUMS);
    float* sgt2          = (float*)(sm + MISC_SGT);
    float* vsuf2         = (float*)(sm + MISC_VSUF);
    float* sMin2         = (float*)(sm + MISC_SMIN);
    float* BP2           = (float*)(sm + MISC_BP);
    float* BPd2          = (float*)(sm + MISC_BPD);
    float* lp2           = (float*)(sm + MISC_LP);
    float* ln2           = (float*)(sm + MISC_LN);
    int*   nsim2         = (int*)(sm + MISC_NSIM);
    int*   ksel2         = (int*)(sm + MISC_KSEL);
    int*   kk2           = (int*)(sm + MISC_KK);
    unsigned* pfx2       = (unsigned*)(sm + MISC_PFX);
    int*   ep2           = (int*)(sm + MISC_EP);
    int*   en2           = (int*)(sm + MISC_EN);
    float* wscrF         = (float*)(sm + SM_WSCR);
    int*   wscrI         = (int*)(sm + SM_WSCR);

    const int tid = threadIdx.x;
    const int lane = tid & 31, wid = tid >> 5;
    const int i0  = blockIdx.x * RPB;

    // ---- async slab load (48 KB), overlapped with mask build ----
    {
        const unsigned rbase = s2u(rows);
        const float* src = g_inner + (size_t)i0 * NROWS;
        #pragma unroll
        for (int i = 0; i < 6; i++) {
            int idx = tid + i * NTHR;
            cpasync16(rbase + (unsigned)idx * 16u, src + (size_t)idx * 4);
        }
        asm volatile("cp.async.commit_group;" ::: "memory");
    }
    const int lab0 = g_label[i0], lab1 = g_label[i0 + 1];
    // packed mask: byte b covers j = 4b..4b+3, bit (jl*2 + r)
    for (int b = tid; b < NROWS / 4; b += NTHR) {
        unsigned m = 0;
        #pragma unroll
        for (int jl = 0; jl < 4; jl++) {
            int l = g_label[4 * b + jl];
            m |= (l == lab0) ? (1u << (jl * 2)) : 0u;
            m |= (l == lab1) ? (1u << (jl * 2 + 1)) : 0u;
        }
        simm[b] = (unsigned char)m;
    }
    for (int t = tid; t < RPB * 256; t += NTHR) hist[t] = 0;
    if (tid < RPB) scnt[tid] = 0;
    asm volatile("cp.async.wait_group 0;" ::: "memory");
    __syncthreads();

    // ---- pass-0: warps 0-1 collect similars | warps 2-15 build count hist ----
    if (wid < RPB) {
        int r = wid;
        int off = 0;
        for (int it = 0; it < NROWS / 32; it++) {
            int j = it * 32 + lane;
            bool s = (simm[j >> 2] >> ((j & 3) * 2 + r)) & 1u;
            unsigned bal = __ballot_sync(0xFFFFFFFFu, s);
            if (s) {
                int pos = off + __popc(bal & ((1u << lane) - 1u));
                if (pos < SIMCAP) simv[r * SIMCAP + pos] = rows[r * NROWS + j];
            }
            off += __popc(bal);
        }
        if (lane == 0) scnt[r] = off;
    } else {
        int w = wid - 2;              // 0..13
        int r = w & 1, seg = w >> 1;  // 7 segs x 896 j per row
        int base = seg * 896;
        for (int it = 0; it < 28; it++) {
            int j = base + it * 32 + lane;
            if (j < NROWS) {
                bool dis = !((simm[j >> 2] >> ((j & 3) * 2 + r)) & 1u);
                float v = rows[r * NROWS + j];
                if (dis) aggHistAdd(hist, r * 256 + (int)(f2key(v) >> 24));
            }
        }
    }
    __syncthreads();

    // ---- sumS + sMin + radix init (threads 0..1) ----
    if (tid < RPB) {
        int r = tid;
        int ns = scnt[r];
        nsim2[r] = ns;
        int nd = NROWS - ns;
        int ks = nd - (nd * 9) / 10;
        if (ks < 1) ks = 1;
        ksel2[r] = ks;
        kk2[r]   = ks;
        int cnt = ns < SIMCAP ? ns : SIMCAP;
        float* sv = simv + r * SIMCAP;
        float sS = 0.f;
        for (int i = 0; i < cnt; i++) sS += sv[i];
        sumS2[r] = sS;
        int m = ns - (ns * 9) / 10;
        if (m < 1) m = 1;
        float ssum = 0.f;
        for (int it = 0; it < m && it < cnt; it++) {
            int bi = it; float bv = sv[it];
            for (int t2 = it + 1; t2 < cnt; t2++) {
                float x = sv[t2];
                if (x < bv) { bv = x; bi = t2; }
            }
            sv[bi] = sv[it]; sv[it] = bv;
            ssum += bv;
        }
        sMin2[r] = clip64(ssum / (float)(m > 1 ? m : 1));
    }
    __syncthreads();

    // ---- radix pass-0 pick (warps 0..1) ----
    if (wid < RPB) {
        int kknext;
        int b0 = radixPick(hist + wid * 256, kk2[wid], lane, &kknext);
        if (lane == 0) { pfx2[wid] = (unsigned)b0; kk2[wid] = kknext; }
    }
    __syncthreads();

    for (int t = tid; t < RPB * 256; t += NTHR) { hist[t] = 0; vhist[t] = 0.f; }
    __syncthreads();

    // ---- refine sweep: sum above byte-0 bin, 16-bit hist inside bin ----
    {
        unsigned p0[2];
        p0[0] = pfx2[0]; p0[1] = pfx2[1];
        float sg[2];
        sg[0] = 0.f; sg[1] = 0.f;
        for (int j = tid; j < NROWS; j += NTHR) {
            unsigned m = (simm[j >> 2] >> ((j & 3) * 2)) & 3u;
            const float* rj = rows + j;
            #pragma unroll
            for (int r = 0; r < RPB; r++) {
                if (!((m >> r) & 1u)) {
                    float v = rj[r * NROWS];
                    unsigned key = f2key(v);
                    unsigned hi = key >> 24;
                    sg[r] += (hi > p0[r]) ? v : 0.f;
                    if (hi == p0[r]) {
                        int bin = (int)((key >> 16) & 255u);
                        atomicAdd(&hist[r * 256 + bin], 1);
                        atomicAdd(&vhist[r * 256 + bin], v);
                    }
                }
            }
        }
        blockSum2F(sg, wscrF, sgt2, tid);
    }

    // ---- pick1 + suffix value sum (warps 0..1) ----
    if (wid < RPB) {
        int kknext;
        int b1 = radixPick(hist + wid * 256, kk2[wid], lane, &kknext);
        int topbin = 255 - lane * 8;
        float vp = 0.f;
        #pragma unroll
        for (int b = 0; b < 8; b++) {
            int bin = topbin - b;
            if (bin > b1) vp += vhist[wid * 256 + bin];
        }
        #pragma unroll
        for (int o = 16; o > 0; o >>= 1) vp += __shfl_xor_sync(0xFFFFFFFFu, vp, o);
        if (lane == 0) {
            float bm = vhist[wid * 256 + b1] / (float)hist[wid * 256 + b1];
            vsuf2[wid] = vp + (float)kknext * bm;
        }
    }
    __syncthreads();

    // ---- thresholds BP/BPd ----
    if (tid < RPB) {
        int r = tid;
        int ns = nsim2[r], nd = NROWS - ns;
        int ks = ksel2[r];
        float sumD = g_rowsum[i0 + r] - sumS2[r];
        float dsum = sgt2[r] + vsuf2[r];
        float dMax = clip64(dsum / (float)(ks > 1 ? ks : 1));
        float meanS  = clip64(sumS2[r] / fmaxf((float)ns, 1.f));
        float meanDS = clip64(sumD / fmaxf((float)nd, 1.f));
        float sMin = sMin2[r];
        BP2[r]  = meanS  - (64.f - meanS) / 64.f * fabsf(meanS - dMax);
        BPd2[r] = meanDS + meanDS / 64.f * fabsf(meanDS - sMin);
    }
    __syncthreads();

    // ---- loss sweep ----
    {
        const float C1 = -0.2871949906334119f;  // C_COEF = -ln(99)/16
        const float C2 = 2.f * C1;              // A_COEF * C_COEF (a == 2 exactly)
        float bp[2], bpd[2];
        bp[0] = BP2[0]; bp[1] = BP2[1];
        bpd[0] = BPd2[0]; bpd[1] = BPd2[1];
        float lp[2], ln_[2]; int ep[2], en[2];
        lp[0] = lp[1] = 0.f; ln_[0] = ln_[1] = 0.f;
        ep[0] = ep[1] = 0; en[0] = en[1] = 0;
        for (int j = tid; j < NROWS; j += NTHR) {
            unsigned m = (simm[j >> 2] >> ((j & 3) * 2)) & 3u;
            const float* rj = rows + j;
            #pragma unroll
            for (int r = 0; r < RPB; r++) {
                float v = rj[r * NROWS];
                bool sim = (m >> r) & 1u;
                float th  = sim ? bp[r] : bpd[r];
                float dc  = v - th;
                float cpos = sim ? C1 : -C2;
                float cneg = sim ? C2 : -C1;
                float f = ((dc > 0.f) ? cpos : cneg) * dc;
                float sp = softplus_f(f);
                bool eq = (dc == 0.f);
                if (sim) { if (eq) ep[r]++; else lp[r] += sp; }
                else     { if (eq) en[r]++; else ln_[r] += sp; }
            }
        }
        blockSum2F(lp, wscrF, lp2, tid);
        blockSum2F(ln_, wscrF, ln2, tid);
        blockSum2I(ep, wscrI, ep2, tid);
        blockSum2I(en, wscrI, en2, tid);
    }

    if (tid < RPB) {
        int r = tid;
        int ns = nsim2[r], nd = NROWS - ns;
        int cp = ns - ep2[r];
        int cn = nd - en2[r];
        g_rowpos[i0 + r] = lp2[r] / fmaxf((float)cp, 1.f);
        g_rowneg[i0 + r] = ln2[r] / fmaxf((float)cn, 1.f);
        g_valid[i0 + r]  = (ns > 0 && nd > 0) ? 1 : 0;
    }
}

// ---------------- kernel 4: final scalar -------------------------------------
__global__ void __launch_bounds__(256) final_kernel(float* __restrict__ out) {
    __shared__ float scrF[8];
    __shared__ int scrI[8];
    int tid = threadIdx.x;
    float ps = 0.f, ns = 0.f; int cv = 0;
    for (int i = tid; i < NROWS; i += 256) {
        if (g_valid[i]) { ps += g_rowpos[i]; ns += g_rowneg[i]; cv++; }
    }
    float q = 0.f;
    for (int i = tid; i < QBLKS; i += 256) q += g_qpart[i];
    #pragma unroll
    for (int o = 16; o > 0; o >>= 1) {
        ps += __shfl_xor_sync(0xFFFFFFFFu, ps, o);
        ns += __shfl_xor_sync(0xFFFFFFFFu, ns, o);
        cv += __shfl_xor_sync(0xFFFFFFFFu, cv, o);
        q  += __shfl_xor_sync(0xFFFFFFFFu, q, o);
    }
    if ((tid & 31) == 0) { scrF[tid >> 5] = ps; scrI[tid >> 5] = cv; }
    __syncthreads();
    __shared__ float scrF2[8]; __shared__ float scrF3[8];
    if ((tid & 31) == 0) { scrF2[tid >> 5] = ns; scrF3[tid >> 5] = q; }
    __syncthreads();
    if (tid == 0) {
        float psum = 0.f, nsum = 0.f, qs = 0.f; int cnt = 0;
        for (int w = 0; w < 8; w++) {
            psum += scrF[w]; nsum += scrF2[w]; qs += scrF3[w]; cnt += scrI[w];
        }
        float posL = (cnt > 0) ? psum / fmaxf((float)cnt, 1.f) : 0.f;
        float navL = (cnt > 0) ? nsum / fmaxf((float)cnt, 1.f) : 0.f;
        float ql = 0.1f * qs / (float)(NROWS * KDIM);
        out[0] = posL + navL + ql;
    }
}

extern "C" void kernel_launch(void* const* d_in, const int* in_sizes, int n_in,
                              void* d_out, int out_size) {
    const float* u = (const float*)d_in[0];
    const int*   y = (const int*)d_in[1];
    (void)in_sizes; (void)n_in; (void)out_size;

    cudaFuncSetAttribute(gemm_sym_kernel,
                         cudaFuncAttributeMaxDynamicSharedMemorySize, GSMEM2);
    cudaFuncSetAttribute(stats_loss_kernel,
                         cudaFuncAttributeMaxDynamicSharedMemorySize, SMEM_BYTES);

    tanh_kernel<<<QBLKS, 256>>>(u);
    label_kernel<<<NROWS * 32 / 256, 256>>>(y);
    colsum_kernel<<<KDIM, 256>>>();
    rowsum_kernel<<<NROWS / 256, 256>>>();
    dim3 ggrid(NROWS / GTT, NROWS / GTT);     // (48, 48), upper triangle active
    gemm_sym_kernel<<<ggrid, GTHR2, GSMEM2>>>();
    stats_loss_kernel<<<NBLK, NTHR, SMEM_BYTES>>>();
    final_kernel<<<1, 256>>>((float*)d_out);
}